// round 13
// baseline (speedup 1.0000x reference)
#include <cuda_runtime.h>
#include <cuda_fp16.h>
#include <cstdint>

#define N_NODES 70000
#define N_EDGES 800000
#define IN_SAGE 1024
#define FEAT_CH 128
#define EXTRA 20
#define HIDDEN 37        // (128+20)/4
#define OUT_CH 3
#define FDIM 1044
#define FC1_IN 148       // FEAT_CH + EXTRA
#define NB ((N_NODES + 255) / 256)   // 274 scan blocks

// ---------------- scratch (device globals; no allocation allowed) ----------
__device__ __align__(16) __half g_ylh[(size_t)N_NODES * FEAT_CH]; // x@Wl^T (fp16)
__device__ float g_yr[(size_t)N_NODES * FEAT_CH];   // x_in @ Wr^T
__device__ __align__(16) __half g_wh[256 * IN_SAGE]; // [Wl;Wr] fp16, pair-interleaved
__device__ int g_deg[N_NODES];
__device__ int g_rowptr[N_NODES];
__device__ int g_cursor[N_NODES];
__device__ int g_csr[N_EDGES];
__device__ int g_bsum[NB];
__device__ int g_boff[NB];

// ---------------- small helpers --------------------------------------------
__device__ __forceinline__ uint32_t smem_u32(const void* p) {
    uint32_t a;
    asm("{ .reg .u64 t; cvta.to.shared.u64 t, %1; cvt.u32.u64 %0, t; }"
        : "=r"(a) : "l"(p));
    return a;
}

// pack (lo, hi) floats -> f16x2 register
__device__ __forceinline__ uint32_t pack_f16x2(float lo, float hi) {
    uint32_t d;
    asm("cvt.rn.f16x2.f32 %0, %1, %2;" : "=r"(d) : "f"(hi), "f"(lo));
    return d;
}

// mma m16n8k16 f16 x f16 -> f32 (base PTX sm_80+, no 'a' feature)
__device__ __forceinline__ void mma_f16(float* c, const uint32_t* a, const uint32_t* b) {
    asm volatile(
        "mma.sync.aligned.m16n8k16.row.col.f32.f16.f16.f32 "
        "{%0,%1,%2,%3},{%4,%5,%6,%7},{%8,%9},{%0,%1,%2,%3};"
        : "+f"(c[0]), "+f"(c[1]), "+f"(c[2]), "+f"(c[3])
        : "r"(a[0]), "r"(a[1]), "r"(a[2]), "r"(a[3]), "r"(b[0]), "r"(b[1]));
}

// ---------------- kernel: weights -> fp16, pair-interleaved ------------------
__global__ void prep_w_kernel(const float* __restrict__ wl, const float* __restrict__ wr) {
    int i = blockIdx.x * blockDim.x + threadIdx.x;
    if (i >= 256 * IN_SAGE) return;
    int n = i >> 10, kk = i & 1023;
    int grp = kk >> 4, within = kk & 15;
    int slot = within >> 1, h = within & 1;
    int p = (slot >> 1) + ((slot & 1) << 2);
    int srck = (grp << 4) + (p << 1) + h;
    float v = (n < 128) ? wl[n * IN_SAGE + srck] : wr[(n - 128) * IN_SAGE + srck];
    g_wh[i] = __float2half_rn(v);
}

// ---------------- CSR build chain -------------------------------------------
__global__ void zero_kernel() {
    int i = blockIdx.x * blockDim.x + threadIdx.x;
    if (i < N_NODES) g_deg[i] = 0;
}

__global__ void hist_kernel(const int* __restrict__ edges) {
    int e = blockIdx.x * blockDim.x + threadIdx.x;
    if (e < N_EDGES) atomicAdd(&g_deg[edges[N_EDGES + e]], 1);
}

__global__ void scan1_kernel() {
    __shared__ int ws[8];
    int i = blockIdx.x * 256 + threadIdx.x;
    int v = (i < N_NODES) ? g_deg[i] : 0;
#pragma unroll
    for (int o = 16; o > 0; o >>= 1) v += __shfl_down_sync(0xffffffffu, v, o);
    if ((threadIdx.x & 31) == 0) ws[threadIdx.x >> 5] = v;
    __syncthreads();
    if (threadIdx.x == 0) {
        int s = 0;
#pragma unroll
        for (int j = 0; j < 8; j++) s += ws[j];
        g_bsum[blockIdx.x] = s;
    }
}

__global__ void scan2_kernel() {
    __shared__ int ss[512];
    int t = threadIdx.x;
    ss[t] = (t < NB) ? g_bsum[t] : 0;
    __syncthreads();
#pragma unroll
    for (int off = 1; off < 512; off <<= 1) {
        int v = (t >= off) ? ss[t - off] : 0;
        __syncthreads();
        ss[t] += v;
        __syncthreads();
    }
    if (t < NB) g_boff[t] = (t > 0) ? ss[t - 1] : 0;
}

__global__ void scan3_kernel() {
    __shared__ int ss[256];
    int t = threadIdx.x;
    int i = blockIdx.x * 256 + t;
    int d = (i < N_NODES) ? g_deg[i] : 0;
    ss[t] = d;
    __syncthreads();
#pragma unroll
    for (int off = 1; off < 256; off <<= 1) {
        int v = (t >= off) ? ss[t - off] : 0;
        __syncthreads();
        ss[t] += v;
        __syncthreads();
    }
    if (i < N_NODES) {
        int pos = g_boff[blockIdx.x] + ss[t] - d;
        g_rowptr[i] = pos;
        g_cursor[i] = pos;
    }
}

__global__ void fill_kernel(const int* __restrict__ edges) {
    int e = blockIdx.x * blockDim.x + threadIdx.x;
    if (e < N_EDGES) {
        int dst = edges[N_EDGES + e];
        int pos = atomicAdd(&g_cursor[dst], 1);
        g_csr[pos] = edges[e];
    }
}

// ---------------- kernel 2: FP16 fused dual GEMM (BM=96) --------------------
// y_l fp16, y_r fp32. 256 thr, 8 warps, warp tile 48x64 (mt=3).
#define GBM 96
#define GBK 32
#define NCH (IN_SAGE / GBK)        // 32
#define AWW 40                     // A words per row (160 B)
#define BWW 24                     // B words per row (96 B)
#define B_OFF_B (GBM * 160)        // 15360 bytes
#define B_OFF_W (B_OFF_B / 4)      // 3840 words
#define STAGE_B (B_OFF_B + 256 * 96)    // 39936 bytes
#define STAGE_W (STAGE_B / 4)           // 9984 words
#define GEMM_SMEM (3 * STAGE_B)         // 119808

__device__ __forceinline__ void issue_stage(
    uint32_t sbase, const float* __restrict__ X, int m0, int k0, int tid)
{
    // A: 96 rows x 32 fp32 -> 768 x 16B / 256 thr = 3 each
#pragma unroll
    for (int it = 0; it < 3; it++) {
        int idx = tid + it * 256;
        int row = idx >> 3, q = idx & 7;
        int m = m0 + row;
        int valid = (m < N_NODES);
        const float* src = X + (size_t)(valid ? m : 0) * FDIM + k0 + q * 4;
        asm volatile("cp.async.cg.shared.global [%0], [%1], 16, %2;"
                     :: "r"(sbase + row * 160 + q * 16), "l"(src),
                        "r"(valid ? 16 : 0));
    }
    // B: 256 rows x 32 fp16 = 64B/row -> 1024 x 16B / 256 thr = 4 each
#pragma unroll
    for (int it = 0; it < 4; it++) {
        int idx = tid + it * 256;
        int row = idx >> 2, q = idx & 3;
        const __half* src = g_wh + (size_t)row * IN_SAGE + k0 + q * 8;
        asm volatile("cp.async.cg.shared.global [%0], [%1], 16;"
                     :: "r"(sbase + B_OFF_B + row * 96 + q * 16), "l"(src));
    }
}

__global__ void __launch_bounds__(256, 1) gemm_kernel(const float* __restrict__ X) {
    extern __shared__ __align__(16) float smf[];
    const uint32_t smb = smem_u32(smf);
    const int tid = threadIdx.x;
    const int wid = tid >> 5;
    const int lane = tid & 31;
    const int gid = lane >> 2;
    const int ctg = lane & 3;
    const int warp_m = wid >> 2;     // 0..1  (M48 each)
    const int warp_n = wid & 3;      // 0..3  (N64 each)
    const int m0 = blockIdx.x * GBM;

    float acc[3][8][4];
#pragma unroll
    for (int i = 0; i < 3; i++)
#pragma unroll
        for (int j = 0; j < 8; j++)
#pragma unroll
            for (int r = 0; r < 4; r++) acc[i][j][r] = 0.0f;

    issue_stage(smb, X, m0, 0, tid);
    asm volatile("cp.async.commit_group;" ::: "memory");
    issue_stage(smb + STAGE_B, X, m0, GBK, tid);
    asm volatile("cp.async.commit_group;" ::: "memory");

    for (int c = 0; c < NCH; c++) {
        asm volatile("cp.async.wait_group 1;" ::: "memory");
        __syncthreads();
        if (c + 2 < NCH)
            issue_stage(smb + ((c + 2) % 3) * STAGE_B, X, m0, (c + 2) * GBK, tid);
        asm volatile("cp.async.commit_group;" ::: "memory");

        const float* st = smf + (c % 3) * STAGE_W;
#pragma unroll
        for (int ks = 0; ks < 2; ks++) {
            uint32_t b[8][2];
#pragma unroll
            for (int nt = 0; nt < 8; nt++) {
                const uint2 bv = *(const uint2*)(st + B_OFF_W +
                    (warp_n * 64 + nt * 8 + gid) * BWW + ks * 8 + 2 * ctg);
                b[nt][0] = bv.x;
                b[nt][1] = bv.y;
            }
            const int kA = ks * 16 + 2 * ctg;
#pragma unroll
            for (int mt = 0; mt < 3; mt++) {
                const float* pa = st + (warp_m * 48 + mt * 16 + gid) * AWW + kA;
                float2 v0 = *(const float2*)(pa);
                float2 v1 = *(const float2*)(pa + 8 * AWW);
                float2 v2 = *(const float2*)(pa + 8);
                float2 v3 = *(const float2*)(pa + 8 * AWW + 8);
                uint32_t a[4];
                a[0] = pack_f16x2(v0.x, v0.y);
                a[1] = pack_f16x2(v1.x, v1.y);
                a[2] = pack_f16x2(v2.x, v2.y);
                a[3] = pack_f16x2(v3.x, v3.y);
#pragma unroll
                for (int nt = 0; nt < 8; nt++)
                    mma_f16(acc[mt][nt], a, b[nt]);
            }
        }
    }

#pragma unroll
    for (int mt = 0; mt < 3; mt++) {
#pragma unroll
        for (int nt = 0; nt < 8; nt++) {
            int col = warp_n * 64 + nt * 8 + 2 * ctg;       // 0..255
            int r0 = m0 + warp_m * 48 + mt * 16 + gid;
            int r1 = r0 + 8;
            if (col < 128) {
                if (r0 < N_NODES)
                    *(uint32_t*)(g_ylh + (size_t)r0 * FEAT_CH + col) =
                        pack_f16x2(acc[mt][nt][0], acc[mt][nt][1]);
                if (r1 < N_NODES)
                    *(uint32_t*)(g_ylh + (size_t)r1 * FEAT_CH + col) =
                        pack_f16x2(acc[mt][nt][2], acc[mt][nt][3]);
            } else {
                int cy = col - 128;
                if (r0 < N_NODES)
                    *(float2*)(g_yr + (size_t)r0 * FEAT_CH + cy) =
                        make_float2(acc[mt][nt][0], acc[mt][nt][1]);
                if (r1 < N_NODES)
                    *(float2*)(g_yr + (size_t)r1 * FEAT_CH + cy) =
                        make_float2(acc[mt][nt][2], acc[mt][nt][3]);
            }
        }
    }
}

// ---------------- kernel 3: FUSED gather + mlp -------------------------------
// 256 nodes/block. Phase A: warp-per-node CSR gather (fp16 y_l rows) ->
// mean+bias+yr+relu -> fp16 pairs in smem (row stride 75 u32, conflict-free)
// plus fp16 extras. Phase B: thread-per-node fc1+BN+fc2.
#define VT_STRIDE 75                         // u32 words per node row
#define OFF_VT 0                             // u32 words
#define OFF_W1 (256 * VT_STRIDE)             // 19200 (16B aligned)
#define OFF_BSS (OFF_W1 + HIDDEN * FC1_IN)   // +5476 = 24676
#define OFF_B1 (OFF_BSS + FEAT_CH)           // 24804
#define OFF_SC (OFF_B1 + HIDDEN)
#define OFF_TR (OFF_SC + HIDDEN)
#define OFF_W2 (OFF_TR + HIDDEN)
#define OFF_B2 (OFF_W2 + OUT_CH * HIDDEN)
#define FUSED_WORDS (OFF_B2 + OUT_CH + 13)
#define FUSED_SMEM (FUSED_WORDS * 4)         // ~100.2 KB

__global__ void __launch_bounds__(256) fused_final(
    const float* __restrict__ feats,
    const float* __restrict__ b_sage,
    const float* __restrict__ fc1_w, const float* __restrict__ fc1_b,
    const float* __restrict__ fc2_w, const float* __restrict__ fc2_b,
    const float* __restrict__ bn_g,  const float* __restrict__ bn_b,
    const float* __restrict__ bn_m,  const float* __restrict__ bn_v,
    float* __restrict__ out)
{
    extern __shared__ __align__(16) uint32_t dyn[];
    uint32_t* vt = dyn + OFF_VT;
    float* w1s = (float*)(dyn + OFF_W1);
    float* bss = (float*)(dyn + OFF_BSS);
    float* b1 = (float*)(dyn + OFF_B1);
    float* sc = (float*)(dyn + OFF_SC);
    float* tr = (float*)(dyn + OFF_TR);
    float* w2s = (float*)(dyn + OFF_W2);
    float* b2 = (float*)(dyn + OFF_B2);

    int tid = threadIdx.x;
    int base = blockIdx.x * 256;

    for (int i = tid; i < HIDDEN * FC1_IN; i += 256) w1s[i] = fc1_w[i];
    for (int i = tid; i < FEAT_CH; i += 256) bss[i] = b_sage[i];
    for (int i = tid; i < OUT_CH * HIDDEN; i += 256) w2s[i] = fc2_w[i];
    if (tid < HIDDEN) {
        b1[tid] = fc1_b[tid];
        float s = bn_g[tid] * rsqrtf(bn_v[tid] + 1e-5f);
        sc[tid] = s;
        tr[tid] = bn_b[tid] - bn_m[tid] * s;
    }
    if (tid < OUT_CH) b2[tid] = fc2_b[tid];
    __syncthreads();

    // ---- phase A: warp per node, 32 nodes per warp ----
    int wid = tid >> 5, lane = tid & 31;
    for (int s = 0; s < 32; s++) {
        int n_off = wid * 32 + s;
        int n = base + n_off;
        if (n >= N_NODES) break;
        int start = g_rowptr[n];
        int deg = g_deg[n];
        int end = start + deg;
        float4 acc = make_float4(0.f, 0.f, 0.f, 0.f);
        int e = start;
        for (; e + 2 <= end; e += 2) {
            int s0 = g_csr[e], s1 = g_csr[e + 1];
            uint2 u0 = *(const uint2*)(g_ylh + (size_t)s0 * FEAT_CH + lane * 4);
            uint2 u1 = *(const uint2*)(g_ylh + (size_t)s1 * FEAT_CH + lane * 4);
            float2 a0 = __half22float2(*reinterpret_cast<__half2*>(&u0.x));
            float2 a1 = __half22float2(*reinterpret_cast<__half2*>(&u0.y));
            float2 c0 = __half22float2(*reinterpret_cast<__half2*>(&u1.x));
            float2 c1 = __half22float2(*reinterpret_cast<__half2*>(&u1.y));
            acc.x += a0.x + c0.x; acc.y += a0.y + c0.y;
            acc.z += a1.x + c1.x; acc.w += a1.y + c1.y;
        }
        if (e < end) {
            int s0 = g_csr[e];
            uint2 u0 = *(const uint2*)(g_ylh + (size_t)s0 * FEAT_CH + lane * 4);
            float2 a0 = __half22float2(*reinterpret_cast<__half2*>(&u0.x));
            float2 a1 = __half22float2(*reinterpret_cast<__half2*>(&u0.y));
            acc.x += a0.x; acc.y += a0.y; acc.z += a1.x; acc.w += a1.y;
        }
        float inv = 1.0f / (float)max(deg, 1);
        float4 yv = *(const float4*)(g_yr + (size_t)n * FEAT_CH + lane * 4);
        int ib = lane * 4;
        float v0 = fmaxf(fmaf(acc.x, inv, bss[ib + 0]) + yv.x, 0.f);
        float v1 = fmaxf(fmaf(acc.y, inv, bss[ib + 1]) + yv.y, 0.f);
        float v2 = fmaxf(fmaf(acc.z, inv, bss[ib + 2]) + yv.z, 0.f);
        float v3 = fmaxf(fmaf(acc.w, inv, bss[ib + 3]) + yv.w, 0.f);
        vt[n_off * VT_STRIDE + lane * 2 + 0] = pack_f16x2(v0, v1);
        vt[n_off * VT_STRIDE + lane * 2 + 1] = pack_f16x2(v2, v3);
        if (lane < 10) {
            float2 ex = *(const float2*)(feats + (size_t)n * FDIM + IN_SAGE + lane * 2);
            vt[n_off * VT_STRIDE + 64 + lane] = pack_f16x2(ex.x, ex.y);
        }
    }
    __syncthreads();

    // ---- phase B: thread per node ----
    int node = base + tid;
    if (node >= N_NODES) return;

    float z[HIDDEN];
#pragma unroll
    for (int j = 0; j < HIDDEN; j++) z[j] = b1[j];

    const uint32_t* vrow = vt + tid * VT_STRIDE;
    for (int g = 0; g < 37; g++) {           // 37 groups of 4 inputs = 148
        uint32_t u0 = vrow[g * 2 + 0];
        uint32_t u1 = vrow[g * 2 + 1];
        float2 f0 = __half22float2(*reinterpret_cast<__half2*>(&u0));
        float2 f1 = __half22float2(*reinterpret_cast<__half2*>(&u1));
        const float4* wp = (const float4*)(w1s + g * 4);
#pragma unroll
        for (int j = 0; j < HIDDEN; j++) {
            float4 w = wp[j * 37];
            z[j] = fmaf(w.x, f0.x, z[j]);
            z[j] = fmaf(w.y, f0.y, z[j]);
            z[j] = fmaf(w.z, f1.x, z[j]);
            z[j] = fmaf(w.w, f1.y, z[j]);
        }
    }

    float h[HIDDEN];
#pragma unroll
    for (int j = 0; j < HIDDEN; j++)
        h[j] = fmaxf(z[j], 0.0f) * sc[j] + tr[j];
#pragma unroll
    for (int k = 0; k < OUT_CH; k++) {
        float s = b2[k];
#pragma unroll
        for (int j = 0; j < HIDDEN; j++)
            s = fmaf(w2s[k * HIDDEN + j], h[j], s);
        out[(size_t)node * OUT_CH + k] = s;
    }
}

// ---------------- launch ----------------------------------------------------
extern "C" void kernel_launch(void* const* d_in, const int* in_sizes, int n_in,
                              void* d_out, int out_size) {
    const float* features = (const float*)d_in[0];
    const int*   edges    = (const int*)  d_in[1];
    // d_in[2] = edges2 (unused), d_in[3] = edge_features (unused)
    const float* w_sage_l = (const float*)d_in[4];
    const float* b_sage_l = (const float*)d_in[5];
    const float* w_sage_r = (const float*)d_in[6];
    const float* fc1_w    = (const float*)d_in[7];
    const float* fc1_b    = (const float*)d_in[8];
    const float* fc2_w    = (const float*)d_in[9];
    const float* fc2_b    = (const float*)d_in[10];
    const float* bn_g     = (const float*)d_in[11];
    const float* bn_b     = (const float*)d_in[12];
    const float* bn_m     = (const float*)d_in[13];
    const float* bn_v     = (const float*)d_in[14];
    float* out = (float*)d_out;

    static cudaStream_t s1 = nullptr;
    static cudaEvent_t evFork = nullptr, evCSR = nullptr;
    if (s1 == nullptr) {
        cudaStreamCreateWithFlags(&s1, cudaStreamNonBlocking);
        cudaEventCreateWithFlags(&evFork, cudaEventDisableTiming);
        cudaEventCreateWithFlags(&evCSR, cudaEventDisableTiming);
    }

    cudaFuncSetAttribute(gemm_kernel,
                         cudaFuncAttributeMaxDynamicSharedMemorySize, GEMM_SMEM);
    cudaFuncSetAttribute(fused_final,
                         cudaFuncAttributeMaxDynamicSharedMemorySize, FUSED_SMEM);

    // fork: CSR build on s1, GEMM on default stream
    cudaEventRecord(evFork, 0);
    cudaStreamWaitEvent(s1, evFork, 0);

    zero_kernel<<<(N_NODES + 255) / 256, 256, 0, s1>>>();
    hist_kernel<<<(N_EDGES + 255) / 256, 256, 0, s1>>>(edges);
    scan1_kernel<<<NB, 256, 0, s1>>>();
    scan2_kernel<<<1, 512, 0, s1>>>();
    scan3_kernel<<<NB, 256, 0, s1>>>();
    fill_kernel<<<(N_EDGES + 255) / 256, 256, 0, s1>>>(edges);
    cudaEventRecord(evCSR, s1);

    prep_w_kernel<<<(256 * IN_SAGE) / 256, 256>>>(w_sage_l, w_sage_r);
    gemm_kernel<<<(N_NODES + GBM - 1) / GBM, 256, GEMM_SMEM>>>(features);

    // join: fused final needs CSR + g_ylh + g_yr
    cudaStreamWaitEvent(0, evCSR, 0);

    fused_final<<<(N_NODES + 255) / 256, 256, FUSED_SMEM>>>(
        features, b_sage_l, fc1_w, fc1_b, fc2_w, fc2_b,
        bn_g, bn_b, bn_m, bn_v, out);
}

// round 14
// speedup vs baseline: 1.0174x; 1.0174x over previous
#include <cuda_runtime.h>
#include <cuda_fp16.h>
#include <cstdint>

#define N_NODES 70000
#define N_EDGES 800000
#define IN_SAGE 1024
#define FEAT_CH 128
#define EXTRA 20
#define HIDDEN 37        // (128+20)/4
#define OUT_CH 3
#define FDIM 1044
#define FC1_IN 148       // FEAT_CH + EXTRA
#define NB ((N_NODES + 255) / 256)   // 274 scan blocks

// ---------------- scratch (device globals; no allocation allowed) ----------
__device__ __align__(16) __half g_ylh[(size_t)N_NODES * FEAT_CH]; // x@Wl^T (fp16)
__device__ float g_yr[(size_t)N_NODES * FEAT_CH];   // x_in @ Wr^T
__device__ __align__(16) __half g_wh[256 * IN_SAGE]; // [Wl;Wr] fp16, pair-interleaved
__device__ int g_deg[N_NODES];
__device__ int g_rowptr[N_NODES];
__device__ int g_cursor[N_NODES];
__device__ int g_csr[N_EDGES];
__device__ int g_bsum[NB];
__device__ int g_boff[NB];

// ---------------- small helpers --------------------------------------------
__device__ __forceinline__ uint32_t smem_u32(const void* p) {
    uint32_t a;
    asm("{ .reg .u64 t; cvta.to.shared.u64 t, %1; cvt.u32.u64 %0, t; }"
        : "=r"(a) : "l"(p));
    return a;
}

// pack (lo, hi) floats -> f16x2 register
__device__ __forceinline__ uint32_t pack_f16x2(float lo, float hi) {
    uint32_t d;
    asm("cvt.rn.f16x2.f32 %0, %1, %2;" : "=r"(d) : "f"(hi), "f"(lo));
    return d;
}

// mma m16n8k16 f16 x f16 -> f32 (base PTX sm_80+, no 'a' feature)
__device__ __forceinline__ void mma_f16(float* c, const uint32_t* a, const uint32_t* b) {
    asm volatile(
        "mma.sync.aligned.m16n8k16.row.col.f32.f16.f16.f32 "
        "{%0,%1,%2,%3},{%4,%5,%6,%7},{%8,%9},{%0,%1,%2,%3};"
        : "+f"(c[0]), "+f"(c[1]), "+f"(c[2]), "+f"(c[3])
        : "r"(a[0]), "r"(a[1]), "r"(a[2]), "r"(a[3]), "r"(b[0]), "r"(b[1]));
}

// ---------------- kernel: weights -> fp16, pair-interleaved ------------------
__global__ void prep_w_kernel(const float* __restrict__ wl, const float* __restrict__ wr) {
    int i = blockIdx.x * blockDim.x + threadIdx.x;
    if (i >= 256 * IN_SAGE) return;
    int n = i >> 10, kk = i & 1023;
    int grp = kk >> 4, within = kk & 15;
    int slot = within >> 1, h = within & 1;
    int p = (slot >> 1) + ((slot & 1) << 2);
    int srck = (grp << 4) + (p << 1) + h;
    float v = (n < 128) ? wl[n * IN_SAGE + srck] : wr[(n - 128) * IN_SAGE + srck];
    g_wh[i] = __float2half_rn(v);
}

// ---------------- CSR build chain -------------------------------------------
__global__ void zero_kernel() {
    int i = blockIdx.x * blockDim.x + threadIdx.x;
    if (i < N_NODES) g_deg[i] = 0;
}

__global__ void hist_kernel(const int* __restrict__ edges) {
    int e = blockIdx.x * blockDim.x + threadIdx.x;
    if (e < N_EDGES) atomicAdd(&g_deg[edges[N_EDGES + e]], 1);
}

__global__ void scan1_kernel() {
    __shared__ int ws[8];
    int i = blockIdx.x * 256 + threadIdx.x;
    int v = (i < N_NODES) ? g_deg[i] : 0;
#pragma unroll
    for (int o = 16; o > 0; o >>= 1) v += __shfl_down_sync(0xffffffffu, v, o);
    if ((threadIdx.x & 31) == 0) ws[threadIdx.x >> 5] = v;
    __syncthreads();
    if (threadIdx.x == 0) {
        int s = 0;
#pragma unroll
        for (int j = 0; j < 8; j++) s += ws[j];
        g_bsum[blockIdx.x] = s;
    }
}

__global__ void scan2_kernel() {
    __shared__ int ss[512];
    int t = threadIdx.x;
    ss[t] = (t < NB) ? g_bsum[t] : 0;
    __syncthreads();
#pragma unroll
    for (int off = 1; off < 512; off <<= 1) {
        int v = (t >= off) ? ss[t - off] : 0;
        __syncthreads();
        ss[t] += v;
        __syncthreads();
    }
    if (t < NB) g_boff[t] = (t > 0) ? ss[t - 1] : 0;
}

__global__ void scan3_kernel() {
    __shared__ int ss[256];
    int t = threadIdx.x;
    int i = blockIdx.x * 256 + t;
    int d = (i < N_NODES) ? g_deg[i] : 0;
    ss[t] = d;
    __syncthreads();
#pragma unroll
    for (int off = 1; off < 256; off <<= 1) {
        int v = (t >= off) ? ss[t - off] : 0;
        __syncthreads();
        ss[t] += v;
        __syncthreads();
    }
    if (i < N_NODES) {
        int pos = g_boff[blockIdx.x] + ss[t] - d;
        g_rowptr[i] = pos;
        g_cursor[i] = pos;
    }
}

__global__ void fill_kernel(const int* __restrict__ edges) {
    int e = blockIdx.x * blockDim.x + threadIdx.x;
    if (e < N_EDGES) {
        int dst = edges[N_EDGES + e];
        int pos = atomicAdd(&g_cursor[dst], 1);
        g_csr[pos] = edges[e];
    }
}

// ---------------- kernel 2: FP16 fused dual GEMM (BM=128, R12 config) -------
// y_l fp16, y_r fp32. 256 thr, 8 warps, warp tile 64x64.
#define GBM 128
#define GBK 32
#define NCH (IN_SAGE / GBK)        // 32
#define AWW 40                     // A words per row (160 B)
#define BWW 24                     // B words per row (96 B)
#define B_OFF_B (128 * 160)        // 20480 bytes
#define B_OFF_W (B_OFF_B / 4)      // 5120 words
#define STAGE_B (B_OFF_B + 256 * 96)    // 45056 bytes
#define STAGE_W (STAGE_B / 4)           // 11264 words
#define GEMM_SMEM (3 * STAGE_B)         // 135168

__device__ __forceinline__ void issue_stage(
    uint32_t sbase, const float* __restrict__ X, int m0, int k0, int tid)
{
#pragma unroll
    for (int it = 0; it < 4; it++) {
        int idx = tid + it * 256;
        int row = idx >> 3, q = idx & 7;
        int m = m0 + row;
        int valid = (m < N_NODES);
        const float* src = X + (size_t)(valid ? m : 0) * FDIM + k0 + q * 4;
        asm volatile("cp.async.cg.shared.global [%0], [%1], 16, %2;"
                     :: "r"(sbase + row * 160 + q * 16), "l"(src),
                        "r"(valid ? 16 : 0));
    }
#pragma unroll
    for (int it = 0; it < 4; it++) {
        int idx = tid + it * 256;
        int row = idx >> 2, q = idx & 3;
        const __half* src = g_wh + (size_t)row * IN_SAGE + k0 + q * 8;
        asm volatile("cp.async.cg.shared.global [%0], [%1], 16;"
                     :: "r"(sbase + B_OFF_B + row * 96 + q * 16), "l"(src));
    }
}

__global__ void __launch_bounds__(256, 1) gemm_kernel(const float* __restrict__ X) {
    extern __shared__ __align__(16) float smf[];
    const uint32_t smb = smem_u32(smf);
    const int tid = threadIdx.x;
    const int wid = tid >> 5;
    const int lane = tid & 31;
    const int gid = lane >> 2;
    const int ctg = lane & 3;
    const int warp_m = wid >> 2;     // 0..1  (M64)
    const int warp_n = wid & 3;      // 0..3  (N64)
    const int m0 = blockIdx.x * GBM;

    float acc[4][8][4];
#pragma unroll
    for (int i = 0; i < 4; i++)
#pragma unroll
        for (int j = 0; j < 8; j++)
#pragma unroll
            for (int r = 0; r < 4; r++) acc[i][j][r] = 0.0f;

    issue_stage(smb, X, m0, 0, tid);
    asm volatile("cp.async.commit_group;" ::: "memory");
    issue_stage(smb + STAGE_B, X, m0, GBK, tid);
    asm volatile("cp.async.commit_group;" ::: "memory");

    for (int c = 0; c < NCH; c++) {
        asm volatile("cp.async.wait_group 1;" ::: "memory");
        __syncthreads();
        if (c + 2 < NCH)
            issue_stage(smb + ((c + 2) % 3) * STAGE_B, X, m0, (c + 2) * GBK, tid);
        asm volatile("cp.async.commit_group;" ::: "memory");

        const float* st = smf + (c % 3) * STAGE_W;
#pragma unroll
        for (int ks = 0; ks < 2; ks++) {
            uint32_t b[8][2];
#pragma unroll
            for (int nt = 0; nt < 8; nt++) {
                const uint2 bv = *(const uint2*)(st + B_OFF_W +
                    (warp_n * 64 + nt * 8 + gid) * BWW + ks * 8 + 2 * ctg);
                b[nt][0] = bv.x;
                b[nt][1] = bv.y;
            }
            const int kA = ks * 16 + 2 * ctg;
#pragma unroll
            for (int mt = 0; mt < 4; mt++) {
                const float* pa = st + (warp_m * 64 + mt * 16 + gid) * AWW + kA;
                float2 v0 = *(const float2*)(pa);
                float2 v1 = *(const float2*)(pa + 8 * AWW);
                float2 v2 = *(const float2*)(pa + 8);
                float2 v3 = *(const float2*)(pa + 8 * AWW + 8);
                uint32_t a[4];
                a[0] = pack_f16x2(v0.x, v0.y);
                a[1] = pack_f16x2(v1.x, v1.y);
                a[2] = pack_f16x2(v2.x, v2.y);
                a[3] = pack_f16x2(v3.x, v3.y);
#pragma unroll
                for (int nt = 0; nt < 8; nt++)
                    mma_f16(acc[mt][nt], a, b[nt]);
            }
        }
    }

#pragma unroll
    for (int mt = 0; mt < 4; mt++) {
#pragma unroll
        for (int nt = 0; nt < 8; nt++) {
            int col = warp_n * 64 + nt * 8 + 2 * ctg;       // 0..255
            int r0 = m0 + warp_m * 64 + mt * 16 + gid;
            int r1 = r0 + 8;
            if (col < 128) {
                if (r0 < N_NODES)
                    *(uint32_t*)(g_ylh + (size_t)r0 * FEAT_CH + col) =
                        pack_f16x2(acc[mt][nt][0], acc[mt][nt][1]);
                if (r1 < N_NODES)
                    *(uint32_t*)(g_ylh + (size_t)r1 * FEAT_CH + col) =
                        pack_f16x2(acc[mt][nt][2], acc[mt][nt][3]);
            } else {
                int cy = col - 128;
                if (r0 < N_NODES)
                    *(float2*)(g_yr + (size_t)r0 * FEAT_CH + cy) =
                        make_float2(acc[mt][nt][0], acc[mt][nt][1]);
                if (r1 < N_NODES)
                    *(float2*)(g_yr + (size_t)r1 * FEAT_CH + cy) =
                        make_float2(acc[mt][nt][2], acc[mt][nt][3]);
            }
        }
    }
}

// ---------------- kernel 3: FUSED gather + mlp -------------------------------
// 256 nodes/block. Phase A: warp-per-node CSR gather (fp16 y_l rows) ->
// mean+bias+yr+relu -> fp16 pairs in smem (row stride 75 u32, conflict-free)
// plus fp16 extras. Phase B: thread-per-node fc1+BN+fc2.
#define VT_STRIDE 75                         // u32 words per node row
#define OFF_VT 0                             // u32 words
#define OFF_W1 (256 * VT_STRIDE)             // 19200 (16B aligned)
#define OFF_BSS (OFF_W1 + HIDDEN * FC1_IN)   // 24676
#define OFF_B1 (OFF_BSS + FEAT_CH)           // 24804
#define OFF_SC (OFF_B1 + HIDDEN)
#define OFF_TR (OFF_SC + HIDDEN)
#define OFF_W2 (OFF_TR + HIDDEN)
#define OFF_B2 (OFF_W2 + OUT_CH * HIDDEN)
#define FUSED_WORDS (OFF_B2 + OUT_CH + 13)
#define FUSED_SMEM (FUSED_WORDS * 4)         // ~100.2 KB

__global__ void __launch_bounds__(256) fused_final(
    const float* __restrict__ feats,
    const float* __restrict__ b_sage,
    const float* __restrict__ fc1_w, const float* __restrict__ fc1_b,
    const float* __restrict__ fc2_w, const float* __restrict__ fc2_b,
    const float* __restrict__ bn_g,  const float* __restrict__ bn_b,
    const float* __restrict__ bn_m,  const float* __restrict__ bn_v,
    float* __restrict__ out)
{
    extern __shared__ __align__(16) uint32_t dyn[];
    uint32_t* vt = dyn + OFF_VT;
    float* w1s = (float*)(dyn + OFF_W1);
    float* bss = (float*)(dyn + OFF_BSS);
    float* b1 = (float*)(dyn + OFF_B1);
    float* sc = (float*)(dyn + OFF_SC);
    float* tr = (float*)(dyn + OFF_TR);
    float* w2s = (float*)(dyn + OFF_W2);
    float* b2 = (float*)(dyn + OFF_B2);

    int tid = threadIdx.x;
    int base = blockIdx.x * 256;

    for (int i = tid; i < HIDDEN * FC1_IN; i += 256) w1s[i] = fc1_w[i];
    for (int i = tid; i < FEAT_CH; i += 256) bss[i] = b_sage[i];
    for (int i = tid; i < OUT_CH * HIDDEN; i += 256) w2s[i] = fc2_w[i];
    if (tid < HIDDEN) {
        b1[tid] = fc1_b[tid];
        float s = bn_g[tid] * rsqrtf(bn_v[tid] + 1e-5f);
        sc[tid] = s;
        tr[tid] = bn_b[tid] - bn_m[tid] * s;
    }
    if (tid < OUT_CH) b2[tid] = fc2_b[tid];
    __syncthreads();

    // ---- phase A: warp per node, 32 nodes per warp ----
    int wid = tid >> 5, lane = tid & 31;
    for (int s = 0; s < 32; s++) {
        int n_off = wid * 32 + s;
        int n = base + n_off;
        if (n >= N_NODES) break;
        int start = g_rowptr[n];
        int deg = g_deg[n];
        int end = start + deg;
        float4 acc = make_float4(0.f, 0.f, 0.f, 0.f);
        int e = start;
        for (; e + 2 <= end; e += 2) {
            int s0 = g_csr[e], s1 = g_csr[e + 1];
            uint2 u0 = *(const uint2*)(g_ylh + (size_t)s0 * FEAT_CH + lane * 4);
            uint2 u1 = *(const uint2*)(g_ylh + (size_t)s1 * FEAT_CH + lane * 4);
            float2 a0 = __half22float2(*reinterpret_cast<__half2*>(&u0.x));
            float2 a1 = __half22float2(*reinterpret_cast<__half2*>(&u0.y));
            float2 c0 = __half22float2(*reinterpret_cast<__half2*>(&u1.x));
            float2 c1 = __half22float2(*reinterpret_cast<__half2*>(&u1.y));
            acc.x += a0.x + c0.x; acc.y += a0.y + c0.y;
            acc.z += a1.x + c1.x; acc.w += a1.y + c1.y;
        }
        if (e < end) {
            int s0 = g_csr[e];
            uint2 u0 = *(const uint2*)(g_ylh + (size_t)s0 * FEAT_CH + lane * 4);
            float2 a0 = __half22float2(*reinterpret_cast<__half2*>(&u0.x));
            float2 a1 = __half22float2(*reinterpret_cast<__half2*>(&u0.y));
            acc.x += a0.x; acc.y += a0.y; acc.z += a1.x; acc.w += a1.y;
        }
        float inv = 1.0f / (float)max(deg, 1);
        float4 yv = *(const float4*)(g_yr + (size_t)n * FEAT_CH + lane * 4);
        int ib = lane * 4;
        float v0 = fmaxf(fmaf(acc.x, inv, bss[ib + 0]) + yv.x, 0.f);
        float v1 = fmaxf(fmaf(acc.y, inv, bss[ib + 1]) + yv.y, 0.f);
        float v2 = fmaxf(fmaf(acc.z, inv, bss[ib + 2]) + yv.z, 0.f);
        float v3 = fmaxf(fmaf(acc.w, inv, bss[ib + 3]) + yv.w, 0.f);
        vt[n_off * VT_STRIDE + lane * 2 + 0] = pack_f16x2(v0, v1);
        vt[n_off * VT_STRIDE + lane * 2 + 1] = pack_f16x2(v2, v3);
        if (lane < 10) {
            float2 ex = *(const float2*)(feats + (size_t)n * FDIM + IN_SAGE + lane * 2);
            vt[n_off * VT_STRIDE + 64 + lane] = pack_f16x2(ex.x, ex.y);
        }
    }
    __syncthreads();

    // ---- phase B: thread per node ----
    int node = base + tid;
    if (node >= N_NODES) return;

    float z[HIDDEN];
#pragma unroll
    for (int j = 0; j < HIDDEN; j++) z[j] = b1[j];

    const uint32_t* vrow = vt + tid * VT_STRIDE;
    for (int g = 0; g < 37; g++) {           // 37 groups of 4 inputs = 148
        uint32_t u0 = vrow[g * 2 + 0];
        uint32_t u1 = vrow[g * 2 + 1];
        float2 f0 = __half22float2(*reinterpret_cast<__half2*>(&u0));
        float2 f1 = __half22float2(*reinterpret_cast<__half2*>(&u1));
        const float4* wp = (const float4*)(w1s + g * 4);
#pragma unroll
        for (int j = 0; j < HIDDEN; j++) {
            float4 w = wp[j * 37];
            z[j] = fmaf(w.x, f0.x, z[j]);
            z[j] = fmaf(w.y, f0.y, z[j]);
            z[j] = fmaf(w.z, f1.x, z[j]);
            z[j] = fmaf(w.w, f1.y, z[j]);
        }
    }

    float h[HIDDEN];
#pragma unroll
    for (int j = 0; j < HIDDEN; j++)
        h[j] = fmaxf(z[j], 0.0f) * sc[j] + tr[j];
#pragma unroll
    for (int k = 0; k < OUT_CH; k++) {
        float s = b2[k];
#pragma unroll
        for (int j = 0; j < HIDDEN; j++)
            s = fmaf(w2s[k * HIDDEN + j], h[j], s);
        out[(size_t)node * OUT_CH + k] = s;
    }
}

// ---------------- launch ----------------------------------------------------
extern "C" void kernel_launch(void* const* d_in, const int* in_sizes, int n_in,
                              void* d_out, int out_size) {
    const float* features = (const float*)d_in[0];
    const int*   edges    = (const int*)  d_in[1];
    // d_in[2] = edges2 (unused), d_in[3] = edge_features (unused)
    const float* w_sage_l = (const float*)d_in[4];
    const float* b_sage_l = (const float*)d_in[5];
    const float* w_sage_r = (const float*)d_in[6];
    const float* fc1_w    = (const float*)d_in[7];
    const float* fc1_b    = (const float*)d_in[8];
    const float* fc2_w    = (const float*)d_in[9];
    const float* fc2_b    = (const float*)d_in[10];
    const float* bn_g     = (const float*)d_in[11];
    const float* bn_b     = (const float*)d_in[12];
    const float* bn_m     = (const float*)d_in[13];
    const float* bn_v     = (const float*)d_in[14];
    float* out = (float*)d_out;

    static cudaStream_t s1 = nullptr;
    static cudaEvent_t evFork = nullptr, evCSR = nullptr;
    if (s1 == nullptr) {
        cudaStreamCreateWithFlags(&s1, cudaStreamNonBlocking);
        cudaEventCreateWithFlags(&evFork, cudaEventDisableTiming);
        cudaEventCreateWithFlags(&evCSR, cudaEventDisableTiming);
    }

    cudaFuncSetAttribute(gemm_kernel,
                         cudaFuncAttributeMaxDynamicSharedMemorySize, GEMM_SMEM);
    cudaFuncSetAttribute(fused_final,
                         cudaFuncAttributeMaxDynamicSharedMemorySize, FUSED_SMEM);

    // fork: CSR build on s1, GEMM on default stream
    cudaEventRecord(evFork, 0);
    cudaStreamWaitEvent(s1, evFork, 0);

    zero_kernel<<<(N_NODES + 255) / 256, 256, 0, s1>>>();
    hist_kernel<<<(N_EDGES + 255) / 256, 256, 0, s1>>>(edges);
    scan1_kernel<<<NB, 256, 0, s1>>>();
    scan2_kernel<<<1, 512, 0, s1>>>();
    scan3_kernel<<<NB, 256, 0, s1>>>();
    fill_kernel<<<(N_EDGES + 255) / 256, 256, 0, s1>>>(edges);
    cudaEventRecord(evCSR, s1);

    prep_w_kernel<<<(256 * IN_SAGE) / 256, 256>>>(w_sage_l, w_sage_r);
    gemm_kernel<<<(N_NODES + GBM - 1) / GBM, 256, GEMM_SMEM>>>(features);

    // join: fused final needs CSR + g_ylh + g_yr
    cudaStreamWaitEvent(0, evCSR, 0);

    fused_final<<<(N_NODES + 255) / 256, 256, FUSED_SMEM>>>(
        features, b_sage_l, fc1_w, fc1_b, fc2_w, fc2_b,
        bn_g, bn_b, bn_m, bn_v, out);
}

// round 15
// speedup vs baseline: 1.1520x; 1.1322x over previous
#include <cuda_runtime.h>
#include <cuda_fp16.h>
#include <cstdint>

#define N_NODES 70000
#define N_EDGES 800000
#define IN_SAGE 1024
#define FEAT_CH 128
#define EXTRA 20
#define HIDDEN 37        // (128+20)/4
#define OUT_CH 3
#define FDIM 1044
#define FC1_IN 148       // FEAT_CH + EXTRA
#define NB ((N_NODES + 255) / 256)   // 274 scan blocks

// ---------------- scratch (device globals; no allocation allowed) ----------
__device__ __align__(16) __half g_ylh[(size_t)N_NODES * FEAT_CH]; // x@Wl^T (fp16)
__device__ float g_yr[(size_t)N_NODES * FEAT_CH];   // x_in @ Wr^T
__device__ __align__(16) uint32_t g_vth[(size_t)N_NODES * 64]; // relu'd fc1 input, f16x2
__device__ __align__(16) __half g_wh[256 * IN_SAGE]; // [Wl;Wr] fp16, pair-interleaved
__device__ int g_deg[N_NODES];
__device__ int g_rowptr[N_NODES];
__device__ int g_cursor[N_NODES];
__device__ int g_csr[N_EDGES];
__device__ int g_bsum[NB];
__device__ int g_boff[NB];

// ---------------- small helpers --------------------------------------------
__device__ __forceinline__ uint32_t smem_u32(const void* p) {
    uint32_t a;
    asm("{ .reg .u64 t; cvta.to.shared.u64 t, %1; cvt.u32.u64 %0, t; }"
        : "=r"(a) : "l"(p));
    return a;
}

// pack (lo, hi) floats -> f16x2 register
__device__ __forceinline__ uint32_t pack_f16x2(float lo, float hi) {
    uint32_t d;
    asm("cvt.rn.f16x2.f32 %0, %1, %2;" : "=r"(d) : "f"(hi), "f"(lo));
    return d;
}

// mma m16n8k16 f16 x f16 -> f32 (base PTX sm_80+, no 'a' feature)
__device__ __forceinline__ void mma_f16(float* c, const uint32_t* a, const uint32_t* b) {
    asm volatile(
        "mma.sync.aligned.m16n8k16.row.col.f32.f16.f16.f32 "
        "{%0,%1,%2,%3},{%4,%5,%6,%7},{%8,%9},{%0,%1,%2,%3};"
        : "+f"(c[0]), "+f"(c[1]), "+f"(c[2]), "+f"(c[3])
        : "r"(a[0]), "r"(a[1]), "r"(a[2]), "r"(a[3]), "r"(b[0]), "r"(b[1]));
}

// ---------------- kernel: weights -> fp16, pair-interleaved ------------------
__global__ void prep_w_kernel(const float* __restrict__ wl, const float* __restrict__ wr) {
    int i = blockIdx.x * blockDim.x + threadIdx.x;
    if (i >= 256 * IN_SAGE) return;
    int n = i >> 10, kk = i & 1023;
    int grp = kk >> 4, within = kk & 15;
    int slot = within >> 1, h = within & 1;
    int p = (slot >> 1) + ((slot & 1) << 2);
    int srck = (grp << 4) + (p << 1) + h;
    float v = (n < 128) ? wl[n * IN_SAGE + srck] : wr[(n - 128) * IN_SAGE + srck];
    g_wh[i] = __float2half_rn(v);
}

// ---------------- CSR build chain -------------------------------------------
__global__ void zero_kernel() {
    int i = blockIdx.x * blockDim.x + threadIdx.x;
    if (i < N_NODES) g_deg[i] = 0;
}

__global__ void hist_kernel(const int* __restrict__ edges) {
    int e = blockIdx.x * blockDim.x + threadIdx.x;
    if (e < N_EDGES) atomicAdd(&g_deg[edges[N_EDGES + e]], 1);
}

__global__ void scan1_kernel() {
    __shared__ int ws[8];
    int i = blockIdx.x * 256 + threadIdx.x;
    int v = (i < N_NODES) ? g_deg[i] : 0;
#pragma unroll
    for (int o = 16; o > 0; o >>= 1) v += __shfl_down_sync(0xffffffffu, v, o);
    if ((threadIdx.x & 31) == 0) ws[threadIdx.x >> 5] = v;
    __syncthreads();
    if (threadIdx.x == 0) {
        int s = 0;
#pragma unroll
        for (int j = 0; j < 8; j++) s += ws[j];
        g_bsum[blockIdx.x] = s;
    }
}

__global__ void scan2_kernel() {
    __shared__ int ss[512];
    int t = threadIdx.x;
    ss[t] = (t < NB) ? g_bsum[t] : 0;
    __syncthreads();
#pragma unroll
    for (int off = 1; off < 512; off <<= 1) {
        int v = (t >= off) ? ss[t - off] : 0;
        __syncthreads();
        ss[t] += v;
        __syncthreads();
    }
    if (t < NB) g_boff[t] = (t > 0) ? ss[t - 1] : 0;
}

__global__ void scan3_kernel() {
    __shared__ int ss[256];
    int t = threadIdx.x;
    int i = blockIdx.x * 256 + t;
    int d = (i < N_NODES) ? g_deg[i] : 0;
    ss[t] = d;
    __syncthreads();
#pragma unroll
    for (int off = 1; off < 256; off <<= 1) {
        int v = (t >= off) ? ss[t - off] : 0;
        __syncthreads();
        ss[t] += v;
        __syncthreads();
    }
    if (i < N_NODES) {
        int pos = g_boff[blockIdx.x] + ss[t] - d;
        g_rowptr[i] = pos;
        g_cursor[i] = pos;
    }
}

__global__ void fill_kernel(const int* __restrict__ edges) {
    int e = blockIdx.x * blockDim.x + threadIdx.x;
    if (e < N_EDGES) {
        int dst = edges[N_EDGES + e];
        int pos = atomicAdd(&g_cursor[dst], 1);
        g_csr[pos] = edges[e];
    }
}

// ---------------- kernel 2: FP16 fused dual GEMM (BM=128, R12 config) -------
#define GBM 128
#define GBK 32
#define NCH (IN_SAGE / GBK)        // 32
#define AWW 40                     // A words per row (160 B)
#define BWW 24                     // B words per row (96 B)
#define B_OFF_B (128 * 160)        // 20480 bytes
#define B_OFF_W (B_OFF_B / 4)      // 5120 words
#define STAGE_B (B_OFF_B + 256 * 96)    // 45056 bytes
#define STAGE_W (STAGE_B / 4)           // 11264 words
#define GEMM_SMEM (3 * STAGE_B)         // 135168

__device__ __forceinline__ void issue_stage(
    uint32_t sbase, const float* __restrict__ X, int m0, int k0, int tid)
{
#pragma unroll
    for (int it = 0; it < 4; it++) {
        int idx = tid + it * 256;
        int row = idx >> 3, q = idx & 7;
        int m = m0 + row;
        int valid = (m < N_NODES);
        const float* src = X + (size_t)(valid ? m : 0) * FDIM + k0 + q * 4;
        asm volatile("cp.async.cg.shared.global [%0], [%1], 16, %2;"
                     :: "r"(sbase + row * 160 + q * 16), "l"(src),
                        "r"(valid ? 16 : 0));
    }
#pragma unroll
    for (int it = 0; it < 4; it++) {
        int idx = tid + it * 256;
        int row = idx >> 2, q = idx & 3;
        const __half* src = g_wh + (size_t)row * IN_SAGE + k0 + q * 8;
        asm volatile("cp.async.cg.shared.global [%0], [%1], 16;"
                     :: "r"(sbase + B_OFF_B + row * 96 + q * 16), "l"(src));
    }
}

__global__ void __launch_bounds__(256, 1) gemm_kernel(const float* __restrict__ X) {
    extern __shared__ __align__(16) float smf[];
    const uint32_t smb = smem_u32(smf);
    const int tid = threadIdx.x;
    const int wid = tid >> 5;
    const int lane = tid & 31;
    const int gid = lane >> 2;
    const int ctg = lane & 3;
    const int warp_m = wid >> 2;     // 0..1  (M64)
    const int warp_n = wid & 3;      // 0..3  (N64)
    const int m0 = blockIdx.x * GBM;

    float acc[4][8][4];
#pragma unroll
    for (int i = 0; i < 4; i++)
#pragma unroll
        for (int j = 0; j < 8; j++)
#pragma unroll
            for (int r = 0; r < 4; r++) acc[i][j][r] = 0.0f;

    issue_stage(smb, X, m0, 0, tid);
    asm volatile("cp.async.commit_group;" ::: "memory");
    issue_stage(smb + STAGE_B, X, m0, GBK, tid);
    asm volatile("cp.async.commit_group;" ::: "memory");

    for (int c = 0; c < NCH; c++) {
        asm volatile("cp.async.wait_group 1;" ::: "memory");
        __syncthreads();
        if (c + 2 < NCH)
            issue_stage(smb + ((c + 2) % 3) * STAGE_B, X, m0, (c + 2) * GBK, tid);
        asm volatile("cp.async.commit_group;" ::: "memory");

        const float* st = smf + (c % 3) * STAGE_W;
#pragma unroll
        for (int ks = 0; ks < 2; ks++) {
            uint32_t b[8][2];
#pragma unroll
            for (int nt = 0; nt < 8; nt++) {
                const uint2 bv = *(const uint2*)(st + B_OFF_W +
                    (warp_n * 64 + nt * 8 + gid) * BWW + ks * 8 + 2 * ctg);
                b[nt][0] = bv.x;
                b[nt][1] = bv.y;
            }
            const int kA = ks * 16 + 2 * ctg;
#pragma unroll
            for (int mt = 0; mt < 4; mt++) {
                const float* pa = st + (warp_m * 64 + mt * 16 + gid) * AWW + kA;
                float2 v0 = *(const float2*)(pa);
                float2 v1 = *(const float2*)(pa + 8 * AWW);
                float2 v2 = *(const float2*)(pa + 8);
                float2 v3 = *(const float2*)(pa + 8 * AWW + 8);
                uint32_t a[4];
                a[0] = pack_f16x2(v0.x, v0.y);
                a[1] = pack_f16x2(v1.x, v1.y);
                a[2] = pack_f16x2(v2.x, v2.y);
                a[3] = pack_f16x2(v3.x, v3.y);
#pragma unroll
                for (int nt = 0; nt < 8; nt++)
                    mma_f16(acc[mt][nt], a, b[nt]);
            }
        }
    }

#pragma unroll
    for (int mt = 0; mt < 4; mt++) {
#pragma unroll
        for (int nt = 0; nt < 8; nt++) {
            int col = warp_n * 64 + nt * 8 + 2 * ctg;       // 0..255
            int r0 = m0 + warp_m * 64 + mt * 16 + gid;
            int r1 = r0 + 8;
            if (col < 128) {
                if (r0 < N_NODES)
                    *(uint32_t*)(g_ylh + (size_t)r0 * FEAT_CH + col) =
                        pack_f16x2(acc[mt][nt][0], acc[mt][nt][1]);
                if (r1 < N_NODES)
                    *(uint32_t*)(g_ylh + (size_t)r1 * FEAT_CH + col) =
                        pack_f16x2(acc[mt][nt][2], acc[mt][nt][3]);
            } else {
                int cy = col - 128;
                if (r0 < N_NODES)
                    *(float2*)(g_yr + (size_t)r0 * FEAT_CH + cy) =
                        make_float2(acc[mt][nt][0], acc[mt][nt][1]);
                if (r1 < N_NODES)
                    *(float2*)(g_yr + (size_t)r1 * FEAT_CH + cy) =
                        make_float2(acc[mt][nt][2], acc[mt][nt][3]);
            }
        }
    }
}

// ---------------- kernel 3: CSR gather + bias + yr + relu -> fp16 ------------
// warp per node (70000 warps). Writes relu'd fc1 input (128 ch) as f16x2.
__global__ __launch_bounds__(256) void gather_kernel(const float* __restrict__ b_sage) {
    int w = (blockIdx.x * blockDim.x + threadIdx.x) >> 5;
    int lane = threadIdx.x & 31;
    if (w >= N_NODES) return;
    float4 bsv = *(const float4*)(b_sage + lane * 4);   // per-lane constant
    int start = g_rowptr[w];
    int deg = g_deg[w];
    int end = start + deg;
    float4 acc = make_float4(0.f, 0.f, 0.f, 0.f);
    int e = start;
    for (; e + 2 <= end; e += 2) {
        int s0 = g_csr[e], s1 = g_csr[e + 1];
        uint2 u0 = *(const uint2*)(g_ylh + (size_t)s0 * FEAT_CH + lane * 4);
        uint2 u1 = *(const uint2*)(g_ylh + (size_t)s1 * FEAT_CH + lane * 4);
        float2 a0 = __half22float2(*reinterpret_cast<__half2*>(&u0.x));
        float2 a1 = __half22float2(*reinterpret_cast<__half2*>(&u0.y));
        float2 c0 = __half22float2(*reinterpret_cast<__half2*>(&u1.x));
        float2 c1 = __half22float2(*reinterpret_cast<__half2*>(&u1.y));
        acc.x += a0.x + c0.x; acc.y += a0.y + c0.y;
        acc.z += a1.x + c1.x; acc.w += a1.y + c1.y;
    }
    if (e < end) {
        int s0 = g_csr[e];
        uint2 u0 = *(const uint2*)(g_ylh + (size_t)s0 * FEAT_CH + lane * 4);
        float2 a0 = __half22float2(*reinterpret_cast<__half2*>(&u0.x));
        float2 a1 = __half22float2(*reinterpret_cast<__half2*>(&u0.y));
        acc.x += a0.x; acc.y += a0.y; acc.z += a1.x; acc.w += a1.y;
    }
    float inv = 1.0f / (float)max(deg, 1);
    float4 yv = *(const float4*)(g_yr + (size_t)w * FEAT_CH + lane * 4);
    float v0 = fmaxf(fmaf(acc.x, inv, bsv.x) + yv.x, 0.f);
    float v1 = fmaxf(fmaf(acc.y, inv, bsv.y) + yv.y, 0.f);
    float v2 = fmaxf(fmaf(acc.z, inv, bsv.z) + yv.z, 0.f);
    float v3 = fmaxf(fmaf(acc.w, inv, bsv.w) + yv.w, 0.f);
    *(uint2*)(g_vth + (size_t)w * 64 + lane * 2) =
        make_uint2(pack_f16x2(v0, v1), pack_f16x2(v2, v3));
}

// ---------------- kernel 4: final MLP (fc1 + BN + fc2) -----------------------
// 256 nodes/block. Stage fp16 rows (64 words) + extras (10 words) into smem
// (stride 75 words, conflict-free), then thread-per-node compute.
#define VTW 75
#define OFF_VT 0
#define OFF_W1 (256 * VTW)                 // 19200 words (16B aligned)
#define OFF_B1 (OFF_W1 + HIDDEN * FC1_IN)  // 24676
#define OFF_SC (OFF_B1 + HIDDEN)
#define OFF_TR (OFF_SC + HIDDEN)
#define OFF_W2 (OFF_TR + HIDDEN)
#define OFF_B2 (OFF_W2 + OUT_CH * HIDDEN)
#define FIN_WORDS (OFF_B2 + OUT_CH + 8)
#define FIN_SMEM (FIN_WORDS * 4)           // ~99.7 KB

__global__ void __launch_bounds__(256) final_kernel(
    const float* __restrict__ feats,
    const float* __restrict__ fc1_w, const float* __restrict__ fc1_b,
    const float* __restrict__ fc2_w, const float* __restrict__ fc2_b,
    const float* __restrict__ bn_g,  const float* __restrict__ bn_b,
    const float* __restrict__ bn_m,  const float* __restrict__ bn_v,
    float* __restrict__ out)
{
    extern __shared__ __align__(16) uint32_t dyn[];
    uint32_t* vt = dyn + OFF_VT;
    float* w1s = (float*)(dyn + OFF_W1);
    float* b1 = (float*)(dyn + OFF_B1);
    float* sc = (float*)(dyn + OFF_SC);
    float* tr = (float*)(dyn + OFF_TR);
    float* w2s = (float*)(dyn + OFF_W2);
    float* b2 = (float*)(dyn + OFF_B2);

    int tid = threadIdx.x;
    int base = blockIdx.x * 256;

    for (int i = tid; i < HIDDEN * FC1_IN; i += 256) w1s[i] = fc1_w[i];
    for (int i = tid; i < OUT_CH * HIDDEN; i += 256) w2s[i] = fc2_w[i];
    if (tid < HIDDEN) {
        b1[tid] = fc1_b[tid];
        float s = bn_g[tid] * rsqrtf(bn_v[tid] + 1e-5f);
        sc[tid] = s;
        tr[tid] = bn_b[tid] - bn_m[tid] * s;
    }
    if (tid < OUT_CH) b2[tid] = fc2_b[tid];

    // stage main 64 words/node: warp w handles nodes w, w+8, ... (coalesced uint2)
    {
        int wrp = tid >> 5, lane = tid & 31;
#pragma unroll
        for (int it = 0; it < 32; it++) {
            int idx = (wrp + (it & 7) * 8) * 32 + lane + (it >> 3) * 0; // placeholder
            (void)idx;
            break;
        }
        // simple form: 256 nodes * 32 uint2 = 8192 uint2 tasks / 256 thr = 32 each
#pragma unroll
        for (int it = 0; it < 32; it++) {
            int idx = tid + it * 256;            // 0..8191
            int n_off = idx >> 5;                // node within block
            int q = idx & 31;                    // uint2 index 0..31
            int n = base + n_off;
            uint2 u = make_uint2(0u, 0u);
            if (n < N_NODES)
                u = *(const uint2*)(g_vth + (size_t)n * 64 + q * 2);
            vt[n_off * VTW + q * 2 + 0] = u.x;
            vt[n_off * VTW + q * 2 + 1] = u.y;
        }
    }
    // stage extras: 20 floats -> 10 f16x2 words per node (thread = node)
    {
        int n = base + tid;
#pragma unroll
        for (int w = 0; w < 5; w++) {
            float4 e = make_float4(0.f, 0.f, 0.f, 0.f);
            if (n < N_NODES)
                e = *(const float4*)(feats + (size_t)n * FDIM + IN_SAGE + w * 4);
            vt[tid * VTW + 64 + w * 2 + 0] = pack_f16x2(e.x, e.y);
            vt[tid * VTW + 64 + w * 2 + 1] = pack_f16x2(e.z, e.w);
        }
    }
    __syncthreads();

    int node = base + tid;
    if (node >= N_NODES) return;

    float z[HIDDEN];
#pragma unroll
    for (int j = 0; j < HIDDEN; j++) z[j] = b1[j];

    const uint32_t* vrow = vt + tid * VTW;
    for (int g = 0; g < 37; g++) {           // 37 groups of 4 inputs = 148
        uint32_t u0 = vrow[g * 2 + 0];
        uint32_t u1 = vrow[g * 2 + 1];
        float2 f0 = __half22float2(*reinterpret_cast<__half2*>(&u0));
        float2 f1 = __half22float2(*reinterpret_cast<__half2*>(&u1));
        const float4* wp = (const float4*)(w1s + g * 4);
#pragma unroll
        for (int j = 0; j < HIDDEN; j++) {
            float4 w = wp[j * 37];
            z[j] = fmaf(w.x, f0.x, z[j]);
            z[j] = fmaf(w.y, f0.y, z[j]);
            z[j] = fmaf(w.z, f1.x, z[j]);
            z[j] = fmaf(w.w, f1.y, z[j]);
        }
    }

    float h[HIDDEN];
#pragma unroll
    for (int j = 0; j < HIDDEN; j++)
        h[j] = fmaxf(z[j], 0.0f) * sc[j] + tr[j];
#pragma unroll
    for (int k = 0; k < OUT_CH; k++) {
        float s = b2[k];
#pragma unroll
        for (int j = 0; j < HIDDEN; j++)
            s = fmaf(w2s[k * HIDDEN + j], h[j], s);
        out[(size_t)node * OUT_CH + k] = s;
    }
}

// ---------------- launch ----------------------------------------------------
extern "C" void kernel_launch(void* const* d_in, const int* in_sizes, int n_in,
                              void* d_out, int out_size) {
    const float* features = (const float*)d_in[0];
    const int*   edges    = (const int*)  d_in[1];
    // d_in[2] = edges2 (unused), d_in[3] = edge_features (unused)
    const float* w_sage_l = (const float*)d_in[4];
    const float* b_sage_l = (const float*)d_in[5];
    const float* w_sage_r = (const float*)d_in[6];
    const float* fc1_w    = (const float*)d_in[7];
    const float* fc1_b    = (const float*)d_in[8];
    const float* fc2_w    = (const float*)d_in[9];
    const float* fc2_b    = (const float*)d_in[10];
    const float* bn_g     = (const float*)d_in[11];
    const float* bn_b     = (const float*)d_in[12];
    const float* bn_m     = (const float*)d_in[13];
    const float* bn_v     = (const float*)d_in[14];
    float* out = (float*)d_out;

    static cudaStream_t s1 = nullptr;
    static cudaEvent_t evFork = nullptr, evCSR = nullptr;
    if (s1 == nullptr) {
        cudaStreamCreateWithFlags(&s1, cudaStreamNonBlocking);
        cudaEventCreateWithFlags(&evFork, cudaEventDisableTiming);
        cudaEventCreateWithFlags(&evCSR, cudaEventDisableTiming);
    }

    cudaFuncSetAttribute(gemm_kernel,
                         cudaFuncAttributeMaxDynamicSharedMemorySize, GEMM_SMEM);
    cudaFuncSetAttribute(final_kernel,
                         cudaFuncAttributeMaxDynamicSharedMemorySize, FIN_SMEM);

    // fork: CSR build on s1, GEMM on default stream
    cudaEventRecord(evFork, 0);
    cudaStreamWaitEvent(s1, evFork, 0);

    zero_kernel<<<(N_NODES + 255) / 256, 256, 0, s1>>>();
    hist_kernel<<<(N_EDGES + 255) / 256, 256, 0, s1>>>(edges);
    scan1_kernel<<<NB, 256, 0, s1>>>();
    scan2_kernel<<<1, 512, 0, s1>>>();
    scan3_kernel<<<NB, 256, 0, s1>>>();
    fill_kernel<<<(N_EDGES + 255) / 256, 256, 0, s1>>>(edges);
    cudaEventRecord(evCSR, s1);

    prep_w_kernel<<<(256 * IN_SAGE) / 256, 256>>>(w_sage_l, w_sage_r);
    gemm_kernel<<<(N_NODES + GBM - 1) / GBM, 256, GEMM_SMEM>>>(features);

    // join: gather needs CSR + g_ylh + g_yr
    cudaStreamWaitEvent(0, evCSR, 0);

    gather_kernel<<<(N_NODES * 32 + 255) / 256, 256>>>(b_sage_l);

    final_kernel<<<NB, 256, FIN_SMEM>>>(
        features, fc1_w, fc1_b, fc2_w, fc2_b,
        bn_g, bn_b, bn_m, bn_v, out);
}

// round 16
// speedup vs baseline: 1.1567x; 1.0041x over previous
#include <cuda_runtime.h>
#include <cuda_fp16.h>
#include <cstdint>

#define N_NODES 70000
#define N_EDGES 800000
#define IN_SAGE 1024
#define FEAT_CH 128
#define EXTRA 20
#define HIDDEN 37        // (128+20)/4
#define OUT_CH 3
#define FDIM 1044
#define FC1_IN 148       // FEAT_CH + EXTRA
#define NB ((N_NODES + 255) / 256)   // 274 scan blocks
#define HALF0 35000
#define HALF1 (N_NODES - HALF0)

// ---------------- scratch (device globals; no allocation allowed) ----------
__device__ __align__(16) __half g_ylh[(size_t)N_NODES * FEAT_CH]; // x@Wl^T (fp16)
__device__ __align__(16) uint32_t g_yrh[(size_t)N_NODES * 64];    // x@Wr^T (f16x2)
__device__ __align__(16) uint32_t g_vth[(size_t)N_NODES * 64];    // relu'd fc1 input
__device__ __align__(16) __half g_wh[256 * IN_SAGE]; // [Wl;Wr] fp16, pair-interleaved
__device__ int g_deg[N_NODES];
__device__ int g_rowptr[N_NODES];
__device__ int g_cursor[N_NODES];
__device__ int g_csr[N_EDGES];
__device__ int g_bsum[NB];
__device__ int g_boff[NB];

// ---------------- small helpers --------------------------------------------
__device__ __forceinline__ uint32_t smem_u32(const void* p) {
    uint32_t a;
    asm("{ .reg .u64 t; cvta.to.shared.u64 t, %1; cvt.u32.u64 %0, t; }"
        : "=r"(a) : "l"(p));
    return a;
}

// pack (lo, hi) floats -> f16x2 register
__device__ __forceinline__ uint32_t pack_f16x2(float lo, float hi) {
    uint32_t d;
    asm("cvt.rn.f16x2.f32 %0, %1, %2;" : "=r"(d) : "f"(hi), "f"(lo));
    return d;
}

// mma m16n8k16 f16 x f16 -> f32 (base PTX sm_80+, no 'a' feature)
__device__ __forceinline__ void mma_f16(float* c, const uint32_t* a, const uint32_t* b) {
    asm volatile(
        "mma.sync.aligned.m16n8k16.row.col.f32.f16.f16.f32 "
        "{%0,%1,%2,%3},{%4,%5,%6,%7},{%8,%9},{%0,%1,%2,%3};"
        : "+f"(c[0]), "+f"(c[1]), "+f"(c[2]), "+f"(c[3])
        : "r"(a[0]), "r"(a[1]), "r"(a[2]), "r"(a[3]), "r"(b[0]), "r"(b[1]));
}

// ---------------- kernel: weights -> fp16, pair-interleaved ------------------
__global__ void prep_w_kernel(const float* __restrict__ wl, const float* __restrict__ wr) {
    int i = blockIdx.x * blockDim.x + threadIdx.x;
    if (i >= 256 * IN_SAGE) return;
    int n = i >> 10, kk = i & 1023;
    int grp = kk >> 4, within = kk & 15;
    int slot = within >> 1, h = within & 1;
    int p = (slot >> 1) + ((slot & 1) << 2);
    int srck = (grp << 4) + (p << 1) + h;
    float v = (n < 128) ? wl[n * IN_SAGE + srck] : wr[(n - 128) * IN_SAGE + srck];
    g_wh[i] = __float2half_rn(v);
}

// ---------------- CSR build chain -------------------------------------------
__global__ void zero_kernel() {
    int i = blockIdx.x * blockDim.x + threadIdx.x;
    if (i < N_NODES) g_deg[i] = 0;
}

__global__ void hist_kernel(const int* __restrict__ edges) {
    int e = blockIdx.x * blockDim.x + threadIdx.x;
    if (e < N_EDGES) atomicAdd(&g_deg[edges[N_EDGES + e]], 1);
}

__global__ void scan1_kernel() {
    __shared__ int ws[8];
    int i = blockIdx.x * 256 + threadIdx.x;
    int v = (i < N_NODES) ? g_deg[i] : 0;
#pragma unroll
    for (int o = 16; o > 0; o >>= 1) v += __shfl_down_sync(0xffffffffu, v, o);
    if ((threadIdx.x & 31) == 0) ws[threadIdx.x >> 5] = v;
    __syncthreads();
    if (threadIdx.x == 0) {
        int s = 0;
#pragma unroll
        for (int j = 0; j < 8; j++) s += ws[j];
        g_bsum[blockIdx.x] = s;
    }
}

__global__ void scan2_kernel() {
    __shared__ int ss[512];
    int t = threadIdx.x;
    ss[t] = (t < NB) ? g_bsum[t] : 0;
    __syncthreads();
#pragma unroll
    for (int off = 1; off < 512; off <<= 1) {
        int v = (t >= off) ? ss[t - off] : 0;
        __syncthreads();
        ss[t] += v;
        __syncthreads();
    }
    if (t < NB) g_boff[t] = (t > 0) ? ss[t - 1] : 0;
}

__global__ void scan3_kernel() {
    __shared__ int ss[256];
    int t = threadIdx.x;
    int i = blockIdx.x * 256 + t;
    int d = (i < N_NODES) ? g_deg[i] : 0;
    ss[t] = d;
    __syncthreads();
#pragma unroll
    for (int off = 1; off < 256; off <<= 1) {
        int v = (t >= off) ? ss[t - off] : 0;
        __syncthreads();
        ss[t] += v;
        __syncthreads();
    }
    if (i < N_NODES) {
        int pos = g_boff[blockIdx.x] + ss[t] - d;
        g_rowptr[i] = pos;
        g_cursor[i] = pos;
    }
}

__global__ void fill_kernel(const int* __restrict__ edges) {
    int e = blockIdx.x * blockDim.x + threadIdx.x;
    if (e < N_EDGES) {
        int dst = edges[N_EDGES + e];
        int pos = atomicAdd(&g_cursor[dst], 1);
        g_csr[pos] = edges[e];
    }
}

// ---------------- kernel 2: FP16 fused dual GEMM (BM=128) -------------------
#define GBM 128
#define GBK 32
#define NCH (IN_SAGE / GBK)        // 32
#define AWW 40                     // A words per row (160 B)
#define BWW 24                     // B words per row (96 B)
#define B_OFF_B (128 * 160)        // 20480 bytes
#define B_OFF_W (B_OFF_B / 4)      // 5120 words
#define STAGE_B (B_OFF_B + 256 * 96)    // 45056 bytes
#define STAGE_W (STAGE_B / 4)           // 11264 words
#define GEMM_SMEM (3 * STAGE_B)         // 135168

__device__ __forceinline__ void issue_stage(
    uint32_t sbase, const float* __restrict__ X, int m0, int k0, int tid)
{
#pragma unroll
    for (int it = 0; it < 4; it++) {
        int idx = tid + it * 256;
        int row = idx >> 3, q = idx & 7;
        int m = m0 + row;
        int valid = (m < N_NODES);
        const float* src = X + (size_t)(valid ? m : 0) * FDIM + k0 + q * 4;
        asm volatile("cp.async.cg.shared.global [%0], [%1], 16, %2;"
                     :: "r"(sbase + row * 160 + q * 16), "l"(src),
                        "r"(valid ? 16 : 0));
    }
#pragma unroll
    for (int it = 0; it < 4; it++) {
        int idx = tid + it * 256;
        int row = idx >> 2, q = idx & 3;
        const __half* src = g_wh + (size_t)row * IN_SAGE + k0 + q * 8;
        asm volatile("cp.async.cg.shared.global [%0], [%1], 16;"
                     :: "r"(sbase + B_OFF_B + row * 96 + q * 16), "l"(src));
    }
}

__global__ void __launch_bounds__(256, 1) gemm_kernel(const float* __restrict__ X) {
    extern __shared__ __align__(16) float smf[];
    const uint32_t smb = smem_u32(smf);
    const int tid = threadIdx.x;
    const int wid = tid >> 5;
    const int lane = tid & 31;
    const int gid = lane >> 2;
    const int ctg = lane & 3;
    const int warp_m = wid >> 2;     // 0..1  (M64)
    const int warp_n = wid & 3;      // 0..3  (N64)
    const int m0 = blockIdx.x * GBM;

    float acc[4][8][4];
#pragma unroll
    for (int i = 0; i < 4; i++)
#pragma unroll
        for (int j = 0; j < 8; j++)
#pragma unroll
            for (int r = 0; r < 4; r++) acc[i][j][r] = 0.0f;

    issue_stage(smb, X, m0, 0, tid);
    asm volatile("cp.async.commit_group;" ::: "memory");
    issue_stage(smb + STAGE_B, X, m0, GBK, tid);
    asm volatile("cp.async.commit_group;" ::: "memory");

    for (int c = 0; c < NCH; c++) {
        asm volatile("cp.async.wait_group 1;" ::: "memory");
        __syncthreads();
        if (c + 2 < NCH)
            issue_stage(smb + ((c + 2) % 3) * STAGE_B, X, m0, (c + 2) * GBK, tid);
        asm volatile("cp.async.commit_group;" ::: "memory");

        const float* st = smf + (c % 3) * STAGE_W;
#pragma unroll
        for (int ks = 0; ks < 2; ks++) {
            uint32_t b[8][2];
#pragma unroll
            for (int nt = 0; nt < 8; nt++) {
                const uint2 bv = *(const uint2*)(st + B_OFF_W +
                    (warp_n * 64 + nt * 8 + gid) * BWW + ks * 8 + 2 * ctg);
                b[nt][0] = bv.x;
                b[nt][1] = bv.y;
            }
            const int kA = ks * 16 + 2 * ctg;
#pragma unroll
            for (int mt = 0; mt < 4; mt++) {
                const float* pa = st + (warp_m * 64 + mt * 16 + gid) * AWW + kA;
                float2 v0 = *(const float2*)(pa);
                float2 v1 = *(const float2*)(pa + 8 * AWW);
                float2 v2 = *(const float2*)(pa + 8);
                float2 v3 = *(const float2*)(pa + 8 * AWW + 8);
                uint32_t a[4];
                a[0] = pack_f16x2(v0.x, v0.y);
                a[1] = pack_f16x2(v1.x, v1.y);
                a[2] = pack_f16x2(v2.x, v2.y);
                a[3] = pack_f16x2(v3.x, v3.y);
#pragma unroll
                for (int nt = 0; nt < 8; nt++)
                    mma_f16(acc[mt][nt], a, b[nt]);
            }
        }
    }

#pragma unroll
    for (int mt = 0; mt < 4; mt++) {
#pragma unroll
        for (int nt = 0; nt < 8; nt++) {
            int col = warp_n * 64 + nt * 8 + 2 * ctg;       // 0..255 (even)
            int r0 = m0 + warp_m * 64 + mt * 16 + gid;
            int r1 = r0 + 8;
            uint32_t p0 = pack_f16x2(acc[mt][nt][0], acc[mt][nt][1]);
            uint32_t p1 = pack_f16x2(acc[mt][nt][2], acc[mt][nt][3]);
            if (col < 128) {
                if (r0 < N_NODES)
                    *(uint32_t*)(g_ylh + (size_t)r0 * FEAT_CH + col) = p0;
                if (r1 < N_NODES)
                    *(uint32_t*)(g_ylh + (size_t)r1 * FEAT_CH + col) = p1;
            } else {
                int cw = (col - 128) >> 1;   // f16x2 word index 0..63
                if (r0 < N_NODES) g_yrh[(size_t)r0 * 64 + cw] = p0;
                if (r1 < N_NODES) g_yrh[(size_t)r1 * 64 + cw] = p1;
            }
        }
    }
}

// ---------------- kernel 3: CSR gather + bias + yr + relu -> fp16 ------------
// warp per node within [node_base, node_base+node_count).
__global__ __launch_bounds__(256) void gather_kernel(
    const float* __restrict__ b_sage, int node_base, int node_count)
{
    int w = (blockIdx.x * blockDim.x + threadIdx.x) >> 5;
    int lane = threadIdx.x & 31;
    if (w >= node_count) return;
    int node = node_base + w;
    float4 bsv = *(const float4*)(b_sage + lane * 4);
    int start = g_rowptr[node];
    int deg = g_deg[node];
    int end = start + deg;
    float4 acc = make_float4(0.f, 0.f, 0.f, 0.f);
    int e = start;
    for (; e + 2 <= end; e += 2) {
        int s0 = g_csr[e], s1 = g_csr[e + 1];
        uint2 u0 = *(const uint2*)(g_ylh + (size_t)s0 * FEAT_CH + lane * 4);
        uint2 u1 = *(const uint2*)(g_ylh + (size_t)s1 * FEAT_CH + lane * 4);
        float2 a0 = __half22float2(*reinterpret_cast<__half2*>(&u0.x));
        float2 a1 = __half22float2(*reinterpret_cast<__half2*>(&u0.y));
        float2 c0 = __half22float2(*reinterpret_cast<__half2*>(&u1.x));
        float2 c1 = __half22float2(*reinterpret_cast<__half2*>(&u1.y));
        acc.x += a0.x + c0.x; acc.y += a0.y + c0.y;
        acc.z += a1.x + c1.x; acc.w += a1.y + c1.y;
    }
    if (e < end) {
        int s0 = g_csr[e];
        uint2 u0 = *(const uint2*)(g_ylh + (size_t)s0 * FEAT_CH + lane * 4);
        float2 a0 = __half22float2(*reinterpret_cast<__half2*>(&u0.x));
        float2 a1 = __half22float2(*reinterpret_cast<__half2*>(&u0.y));
        acc.x += a0.x; acc.y += a0.y; acc.z += a1.x; acc.w += a1.y;
    }
    float inv = 1.0f / (float)max(deg, 1);
    uint2 uy = *(const uint2*)(g_yrh + (size_t)node * 64 + lane * 2);
    float2 y0 = __half22float2(*reinterpret_cast<__half2*>(&uy.x));
    float2 y1 = __half22float2(*reinterpret_cast<__half2*>(&uy.y));
    float v0 = fmaxf(fmaf(acc.x, inv, bsv.x) + y0.x, 0.f);
    float v1 = fmaxf(fmaf(acc.y, inv, bsv.y) + y0.y, 0.f);
    float v2 = fmaxf(fmaf(acc.z, inv, bsv.z) + y1.x, 0.f);
    float v3 = fmaxf(fmaf(acc.w, inv, bsv.w) + y1.y, 0.f);
    *(uint2*)(g_vth + (size_t)node * 64 + lane * 2) =
        make_uint2(pack_f16x2(v0, v1), pack_f16x2(v2, v3));
}

// ---------------- kernel 4: final MLP (fc1 + BN + fc2) -----------------------
#define VTW 75
#define OFF_VT 0
#define OFF_W1 (256 * VTW)                 // 19200 words (16B aligned)
#define OFF_B1 (OFF_W1 + HIDDEN * FC1_IN)  // 24676
#define OFF_SC (OFF_B1 + HIDDEN)
#define OFF_TR (OFF_SC + HIDDEN)
#define OFF_W2 (OFF_TR + HIDDEN)
#define OFF_B2 (OFF_W2 + OUT_CH * HIDDEN)
#define FIN_WORDS (OFF_B2 + OUT_CH + 8)
#define FIN_SMEM (FIN_WORDS * 4)           // ~99.7 KB

__global__ void __launch_bounds__(256) final_kernel(
    const float* __restrict__ feats,
    const float* __restrict__ fc1_w, const float* __restrict__ fc1_b,
    const float* __restrict__ fc2_w, const float* __restrict__ fc2_b,
    const float* __restrict__ bn_g,  const float* __restrict__ bn_b,
    const float* __restrict__ bn_m,  const float* __restrict__ bn_v,
    float* __restrict__ out, int node_base)
{
    extern __shared__ __align__(16) uint32_t dyn[];
    uint32_t* vt = dyn + OFF_VT;
    float* w1s = (float*)(dyn + OFF_W1);
    float* b1 = (float*)(dyn + OFF_B1);
    float* sc = (float*)(dyn + OFF_SC);
    float* tr = (float*)(dyn + OFF_TR);
    float* w2s = (float*)(dyn + OFF_W2);
    float* b2 = (float*)(dyn + OFF_B2);

    int tid = threadIdx.x;
    int base = node_base + blockIdx.x * 256;

    for (int i = tid; i < HIDDEN * FC1_IN; i += 256) w1s[i] = fc1_w[i];
    for (int i = tid; i < OUT_CH * HIDDEN; i += 256) w2s[i] = fc2_w[i];
    if (tid < HIDDEN) {
        b1[tid] = fc1_b[tid];
        float s = bn_g[tid] * rsqrtf(bn_v[tid] + 1e-5f);
        sc[tid] = s;
        tr[tid] = bn_b[tid] - bn_m[tid] * s;
    }
    if (tid < OUT_CH) b2[tid] = fc2_b[tid];

    // stage main 64 words/node (coalesced uint2)
#pragma unroll
    for (int it = 0; it < 32; it++) {
        int idx = tid + it * 256;            // 0..8191
        int n_off = idx >> 5;
        int q = idx & 31;
        int n = base + n_off;
        uint2 u = make_uint2(0u, 0u);
        if (n < N_NODES)
            u = *(const uint2*)(g_vth + (size_t)n * 64 + q * 2);
        vt[n_off * VTW + q * 2 + 0] = u.x;
        vt[n_off * VTW + q * 2 + 1] = u.y;
    }
    // stage extras: 20 floats -> 10 f16x2 words per node
    {
        int n = base + tid;
#pragma unroll
        for (int w = 0; w < 5; w++) {
            float4 e = make_float4(0.f, 0.f, 0.f, 0.f);
            if (n < N_NODES)
                e = *(const float4*)(feats + (size_t)n * FDIM + IN_SAGE + w * 4);
            vt[tid * VTW + 64 + w * 2 + 0] = pack_f16x2(e.x, e.y);
            vt[tid * VTW + 64 + w * 2 + 1] = pack_f16x2(e.z, e.w);
        }
    }
    __syncthreads();

    int node = base + tid;
    if (node >= N_NODES) return;

    float z[HIDDEN];
#pragma unroll
    for (int j = 0; j < HIDDEN; j++) z[j] = b1[j];

    const uint32_t* vrow = vt + tid * VTW;
    for (int g = 0; g < 37; g++) {
        uint32_t u0 = vrow[g * 2 + 0];
        uint32_t u1 = vrow[g * 2 + 1];
        float2 f0 = __half22float2(*reinterpret_cast<__half2*>(&u0));
        float2 f1 = __half22float2(*reinterpret_cast<__half2*>(&u1));
        const float4* wp = (const float4*)(w1s + g * 4);
#pragma unroll
        for (int j = 0; j < HIDDEN; j++) {
            float4 w = wp[j * 37];
            z[j] = fmaf(w.x, f0.x, z[j]);
            z[j] = fmaf(w.y, f0.y, z[j]);
            z[j] = fmaf(w.z, f1.x, z[j]);
            z[j] = fmaf(w.w, f1.y, z[j]);
        }
    }

    float h[HIDDEN];
#pragma unroll
    for (int j = 0; j < HIDDEN; j++)
        h[j] = fmaxf(z[j], 0.0f) * sc[j] + tr[j];
#pragma unroll
    for (int k = 0; k < OUT_CH; k++) {
        float s = b2[k];
#pragma unroll
        for (int j = 0; j < HIDDEN; j++)
            s = fmaf(w2s[k * HIDDEN + j], h[j], s);
        out[(size_t)node * OUT_CH + k] = s;
    }
}

// ---------------- launch ----------------------------------------------------
extern "C" void kernel_launch(void* const* d_in, const int* in_sizes, int n_in,
                              void* d_out, int out_size) {
    const float* features = (const float*)d_in[0];
    const int*   edges    = (const int*)  d_in[1];
    // d_in[2] = edges2 (unused), d_in[3] = edge_features (unused)
    const float* w_sage_l = (const float*)d_in[4];
    const float* b_sage_l = (const float*)d_in[5];
    const float* w_sage_r = (const float*)d_in[6];
    const float* fc1_w    = (const float*)d_in[7];
    const float* fc1_b    = (const float*)d_in[8];
    const float* fc2_w    = (const float*)d_in[9];
    const float* fc2_b    = (const float*)d_in[10];
    const float* bn_g     = (const float*)d_in[11];
    const float* bn_b     = (const float*)d_in[12];
    const float* bn_m     = (const float*)d_in[13];
    const float* bn_v     = (const float*)d_in[14];
    float* out = (float*)d_out;

    static cudaStream_t s1 = nullptr;
    static cudaEvent_t evFork = nullptr, evCSR = nullptr, evG0 = nullptr, evG1 = nullptr;
    if (s1 == nullptr) {
        cudaStreamCreateWithFlags(&s1, cudaStreamNonBlocking);
        cudaEventCreateWithFlags(&evFork, cudaEventDisableTiming);
        cudaEventCreateWithFlags(&evCSR, cudaEventDisableTiming);
        cudaEventCreateWithFlags(&evG0, cudaEventDisableTiming);
        cudaEventCreateWithFlags(&evG1, cudaEventDisableTiming);
    }

    cudaFuncSetAttribute(gemm_kernel,
                         cudaFuncAttributeMaxDynamicSharedMemorySize, GEMM_SMEM);
    cudaFuncSetAttribute(final_kernel,
                         cudaFuncAttributeMaxDynamicSharedMemorySize, FIN_SMEM);

    // fork: CSR build on s1, GEMM on default stream
    cudaEventRecord(evFork, 0);
    cudaStreamWaitEvent(s1, evFork, 0);

    zero_kernel<<<(N_NODES + 255) / 256, 256, 0, s1>>>();
    hist_kernel<<<(N_EDGES + 255) / 256, 256, 0, s1>>>(edges);
    scan1_kernel<<<NB, 256, 0, s1>>>();
    scan2_kernel<<<1, 512, 0, s1>>>();
    scan3_kernel<<<NB, 256, 0, s1>>>();
    fill_kernel<<<(N_EDGES + 255) / 256, 256, 0, s1>>>(edges);
    cudaEventRecord(evCSR, s1);

    prep_w_kernel<<<(256 * IN_SAGE) / 256, 256>>>(w_sage_l, w_sage_r);
    gemm_kernel<<<(N_NODES + GBM - 1) / GBM, 256, GEMM_SMEM>>>(features);

    // join CSR, then pipeline: gather0 -> (final0 || gather1) -> final1
    cudaStreamWaitEvent(0, evCSR, 0);

    gather_kernel<<<(HALF0 * 32 + 255) / 256, 256>>>(b_sage_l, 0, HALF0);
    cudaEventRecord(evG0, 0);

    cudaStreamWaitEvent(s1, evG0, 0);
    gather_kernel<<<(HALF1 * 32 + 255) / 256, 256, 0, s1>>>(b_sage_l, HALF0, HALF1);
    cudaEventRecord(evG1, s1);

    final_kernel<<<(HALF0 + 255) / 256, 256, FIN_SMEM>>>(
        features, fc1_w, fc1_b, fc2_w, fc2_b,
        bn_g, bn_b, bn_m, bn_v, out, 0);

    cudaStreamWaitEvent(0, evG1, 0);
    final_kernel<<<(HALF1 + 255) / 256, 256, FIN_SMEM>>>(
        features, fc1_w, fc1_b, fc2_w, fc2_b,
        bn_g, bn_b, bn_m, bn_v, out, HALF0);
}

// round 17
// speedup vs baseline: 1.1861x; 1.0255x over previous
#include <cuda_runtime.h>
#include <cuda_fp16.h>
#include <cstdint>

#define N_NODES 70000
#define N_EDGES 800000
#define IN_SAGE 1024
#define FEAT_CH 128
#define EXTRA 20
#define HIDDEN 37        // (128+20)/4
#define OUT_CH 3
#define FDIM 1044
#define FC1_IN 148       // FEAT_CH + EXTRA
#define NB ((N_NODES + 255) / 256)   // 274 scan blocks
#define HALF0 35000
#define HALF1 (N_NODES - HALF0)

// ---------------- scratch (device globals; no allocation allowed) ----------
__device__ __align__(16) __half g_ylh[(size_t)N_NODES * FEAT_CH]; // x@Wl^T (fp16)
__device__ __align__(16) uint32_t g_yrh[(size_t)N_NODES * 64];    // x@Wr^T (f16x2)
__device__ __align__(16) uint32_t g_vth[(size_t)N_NODES * 64];    // relu'd fc1 input
__device__ __align__(16) __half g_wh[256 * IN_SAGE]; // [Wl;Wr] fp16, pair-interleaved
__device__ int g_deg[N_NODES];
__device__ int g_rowptr[N_NODES];
__device__ int g_cursor[N_NODES];
__device__ int g_csr[N_EDGES];
__device__ int g_bsum[NB];
__device__ int g_boff[NB];

// ---------------- small helpers --------------------------------------------
__device__ __forceinline__ uint32_t smem_u32(const void* p) {
    uint32_t a;
    asm("{ .reg .u64 t; cvta.to.shared.u64 t, %1; cvt.u32.u64 %0, t; }"
        : "=r"(a) : "l"(p));
    return a;
}

// pack (lo, hi) floats -> f16x2 register
__device__ __forceinline__ uint32_t pack_f16x2(float lo, float hi) {
    uint32_t d;
    asm("cvt.rn.f16x2.f32 %0, %1, %2;" : "=r"(d) : "f"(hi), "f"(lo));
    return d;
}

// mma m16n8k16 f16 x f16 -> f32 (base PTX sm_80+, no 'a' feature)
__device__ __forceinline__ void mma_f16(float* c, const uint32_t* a, const uint32_t* b) {
    asm volatile(
        "mma.sync.aligned.m16n8k16.row.col.f32.f16.f16.f32 "
        "{%0,%1,%2,%3},{%4,%5,%6,%7},{%8,%9},{%0,%1,%2,%3};"
        : "+f"(c[0]), "+f"(c[1]), "+f"(c[2]), "+f"(c[3])
        : "r"(a[0]), "r"(a[1]), "r"(a[2]), "r"(a[3]), "r"(b[0]), "r"(b[1]));
}

// ---------------- kernel: weights -> fp16, pair-interleaved ------------------
__global__ void prep_w_kernel(const float* __restrict__ wl, const float* __restrict__ wr) {
    int i = blockIdx.x * blockDim.x + threadIdx.x;
    if (i >= 256 * IN_SAGE) return;
    int n = i >> 10, kk = i & 1023;
    int grp = kk >> 4, within = kk & 15;
    int slot = within >> 1, h = within & 1;
    int p = (slot >> 1) + ((slot & 1) << 2);
    int srck = (grp << 4) + (p << 1) + h;
    float v = (n < 128) ? wl[n * IN_SAGE + srck] : wr[(n - 128) * IN_SAGE + srck];
    g_wh[i] = __float2half_rn(v);
}

// ---------------- CSR build chain -------------------------------------------
__global__ void zero_kernel() {
    int i = blockIdx.x * blockDim.x + threadIdx.x;
    if (i < N_NODES) g_deg[i] = 0;
}

__global__ void hist_kernel(const int* __restrict__ edges) {
    int e = blockIdx.x * blockDim.x + threadIdx.x;
    if (e < N_EDGES) atomicAdd(&g_deg[edges[N_EDGES + e]], 1);
}

__global__ void scan1_kernel() {
    __shared__ int ws[8];
    int i = blockIdx.x * 256 + threadIdx.x;
    int v = (i < N_NODES) ? g_deg[i] : 0;
#pragma unroll
    for (int o = 16; o > 0; o >>= 1) v += __shfl_down_sync(0xffffffffu, v, o);
    if ((threadIdx.x & 31) == 0) ws[threadIdx.x >> 5] = v;
    __syncthreads();
    if (threadIdx.x == 0) {
        int s = 0;
#pragma unroll
        for (int j = 0; j < 8; j++) s += ws[j];
        g_bsum[blockIdx.x] = s;
    }
}

__global__ void scan2_kernel() {
    __shared__ int ss[512];
    int t = threadIdx.x;
    ss[t] = (t < NB) ? g_bsum[t] : 0;
    __syncthreads();
#pragma unroll
    for (int off = 1; off < 512; off <<= 1) {
        int v = (t >= off) ? ss[t - off] : 0;
        __syncthreads();
        ss[t] += v;
        __syncthreads();
    }
    if (t < NB) g_boff[t] = (t > 0) ? ss[t - 1] : 0;
}

__global__ void scan3_kernel() {
    __shared__ int ss[256];
    int t = threadIdx.x;
    int i = blockIdx.x * 256 + t;
    int d = (i < N_NODES) ? g_deg[i] : 0;
    ss[t] = d;
    __syncthreads();
#pragma unroll
    for (int off = 1; off < 256; off <<= 1) {
        int v = (t >= off) ? ss[t - off] : 0;
        __syncthreads();
        ss[t] += v;
        __syncthreads();
    }
    if (i < N_NODES) {
        int pos = g_boff[blockIdx.x] + ss[t] - d;
        g_rowptr[i] = pos;
        g_cursor[i] = pos;
    }
}

__global__ void fill_kernel(const int* __restrict__ edges) {
    int e = blockIdx.x * blockDim.x + threadIdx.x;
    if (e < N_EDGES) {
        int dst = edges[N_EDGES + e];
        int pos = atomicAdd(&g_cursor[dst], 1);
        g_csr[pos] = edges[e];
    }
}

// ---------------- kernel 2: FP16 dual GEMM, A fp16 in smem -------------------
// A: fp16 pair-interleaved, row stride 40 words (160 B). Producer: LDG fp32 ->
// cvt -> STS, prefetched one chunk ahead. B: cp.async fp16 (unchanged).
#define GBM 128
#define GBK 32
#define NCH (IN_SAGE / GBK)        // 32
#define AWW 40                     // A row stride in u32 words (160 B)
#define BWW 24                     // B words per row (96 B)
#define B_OFF_B (128 * 160)        // 20480 bytes
#define B_OFF_W (B_OFF_B / 4)      // 5120 words
#define STAGE_B (B_OFF_B + 256 * 96)    // 45056 bytes
#define STAGE_W (STAGE_B / 4)           // 11264 words
#define GEMM_SMEM (3 * STAGE_B)         // 135168

// load one (row, 16k-half) of X into 4 float4 regs
__device__ __forceinline__ void ldgA(
    const float* __restrict__ X, int m0, int k0, int tid, float4* r)
{
    int row = tid >> 1, half = tid & 1;
    int m = m0 + row;
    const float* src = X + (size_t)((m < N_NODES) ? m : 0) * FDIM + k0 + half * 16;
    if (m < N_NODES) {
        r[0] = *(const float4*)(src + 0);
        r[1] = *(const float4*)(src + 4);
        r[2] = *(const float4*)(src + 8);
        r[3] = *(const float4*)(src + 12);
    } else {
        r[0] = r[1] = r[2] = r[3] = make_float4(0.f, 0.f, 0.f, 0.f);
    }
}

// convert + store to interleaved fp16 A tile
__device__ __forceinline__ void stsA(float* stage, int tid, const float4* r) {
    int row = tid >> 1, half = tid & 1;
    // slots [p0,p4,p1,p5,p2,p6,p3,p7]; r0=k0..3 r1=k4..7 r2=k8..11 r3=k12..15
    uint32_t s0 = pack_f16x2(r[0].x, r[0].y);   // p0
    uint32_t s2 = pack_f16x2(r[0].z, r[0].w);   // p1
    uint32_t s4 = pack_f16x2(r[1].x, r[1].y);   // p2
    uint32_t s6 = pack_f16x2(r[1].z, r[1].w);   // p3
    uint32_t s1 = pack_f16x2(r[2].x, r[2].y);   // p4
    uint32_t s3 = pack_f16x2(r[2].z, r[2].w);   // p5
    uint32_t s5 = pack_f16x2(r[3].x, r[3].y);   // p6
    uint32_t s7 = pack_f16x2(r[3].z, r[3].w);   // p7
    uint32_t* dst = (uint32_t*)stage + row * AWW + half * 8;
    *(uint4*)(dst + 0) = make_uint4(s0, s1, s2, s3);
    *(uint4*)(dst + 4) = make_uint4(s4, s5, s6, s7);
}

__device__ __forceinline__ void issue_B(
    uint32_t sbase, int k0, int tid)
{
#pragma unroll
    for (int it = 0; it < 4; it++) {
        int idx = tid + it * 256;
        int row = idx >> 2, q = idx & 3;
        const __half* src = g_wh + (size_t)row * IN_SAGE + k0 + q * 8;
        asm volatile("cp.async.cg.shared.global [%0], [%1], 16;"
                     :: "r"(sbase + B_OFF_B + row * 96 + q * 16), "l"(src));
    }
}

__global__ void __launch_bounds__(256, 1) gemm_kernel(const float* __restrict__ X) {
    extern __shared__ __align__(16) float smf[];
    const uint32_t smb = smem_u32(smf);
    const int tid = threadIdx.x;
    const int wid = tid >> 5;
    const int lane = tid & 31;
    const int gid = lane >> 2;
    const int ctg = lane & 3;
    const int warp_m = wid >> 2;     // 0..1  (M64)
    const int warp_n = wid & 3;      // 0..3  (N64)
    const int m0 = blockIdx.x * GBM;

    float acc[4][8][4];
#pragma unroll
    for (int i = 0; i < 4; i++)
#pragma unroll
        for (int j = 0; j < 8; j++)
#pragma unroll
            for (int r = 0; r < 4; r++) acc[i][j][r] = 0.0f;

    float4 ra[4];
    // prologue: A chunk0 to stage0; prefetch A chunk1; B chunks 0,1 via cp.async
    ldgA(X, m0, 0, tid, ra);
    stsA(smf, tid, ra);
    ldgA(X, m0, GBK, tid, ra);
    issue_B(smb, 0, tid);
    asm volatile("cp.async.commit_group;" ::: "memory");
    issue_B(smb + STAGE_B, GBK, tid);
    asm volatile("cp.async.commit_group;" ::: "memory");

    for (int c = 0; c < NCH; c++) {
        asm volatile("cp.async.wait_group 1;" ::: "memory");
        __syncthreads();
        if (c + 1 < NCH)
            stsA(smf + ((c + 1) % 3) * STAGE_W, tid, ra);
        if (c + 2 < NCH) {
            ldgA(X, m0, (c + 2) * GBK, tid, ra);
            issue_B(smb + ((c + 2) % 3) * STAGE_B, (c + 2) * GBK, tid);
        }
        asm volatile("cp.async.commit_group;" ::: "memory");

        const float* st = smf + (c % 3) * STAGE_W;
#pragma unroll
        for (int ks = 0; ks < 2; ks++) {
            uint32_t b[8][2];
#pragma unroll
            for (int nt = 0; nt < 8; nt++) {
                const uint2 bv = *(const uint2*)(st + B_OFF_W +
                    (warp_n * 64 + nt * 8 + gid) * BWW + ks * 8 + 2 * ctg);
                b[nt][0] = bv.x;
                b[nt][1] = bv.y;
            }
#pragma unroll
            for (int mt = 0; mt < 4; mt++) {
                const uint32_t* pa = (const uint32_t*)st +
                    (warp_m * 64 + mt * 16 + gid) * AWW + ks * 8 + 2 * ctg;
                uint2 ua = *(const uint2*)pa;             // (row,k..k+1),(row,k+8..k+9)
                uint2 ub = *(const uint2*)(pa + 8 * AWW); // row+8
                uint32_t a[4];
                a[0] = ua.x; a[1] = ub.x; a[2] = ua.y; a[3] = ub.y;
#pragma unroll
                for (int nt = 0; nt < 8; nt++)
                    mma_f16(acc[mt][nt], a, b[nt]);
            }
        }
    }

#pragma unroll
    for (int mt = 0; mt < 4; mt++) {
#pragma unroll
        for (int nt = 0; nt < 8; nt++) {
            int col = warp_n * 64 + nt * 8 + 2 * ctg;       // 0..255 (even)
            int r0 = m0 + warp_m * 64 + mt * 16 + gid;
            int r1 = r0 + 8;
            uint32_t p0 = pack_f16x2(acc[mt][nt][0], acc[mt][nt][1]);
            uint32_t p1 = pack_f16x2(acc[mt][nt][2], acc[mt][nt][3]);
            if (col < 128) {
                if (r0 < N_NODES)
                    *(uint32_t*)(g_ylh + (size_t)r0 * FEAT_CH + col) = p0;
                if (r1 < N_NODES)
                    *(uint32_t*)(g_ylh + (size_t)r1 * FEAT_CH + col) = p1;
            } else {
                int cw = (col - 128) >> 1;   // f16x2 word index 0..63
                if (r0 < N_NODES) g_yrh[(size_t)r0 * 64 + cw] = p0;
                if (r1 < N_NODES) g_yrh[(size_t)r1 * 64 + cw] = p1;
            }
        }
    }
}

// ---------------- kernel 3: CSR gather + bias + yr + relu -> fp16 ------------
__global__ __launch_bounds__(256) void gather_kernel(
    const float* __restrict__ b_sage, int node_base, int node_count)
{
    int w = (blockIdx.x * blockDim.x + threadIdx.x) >> 5;
    int lane = threadIdx.x & 31;
    if (w >= node_count) return;
    int node = node_base + w;
    float4 bsv = *(const float4*)(b_sage + lane * 4);
    int start = g_rowptr[node];
    int deg = g_deg[node];
    int end = start + deg;
    float4 acc = make_float4(0.f, 0.f, 0.f, 0.f);
    int e = start;
    for (; e + 2 <= end; e += 2) {
        int s0 = g_csr[e], s1 = g_csr[e + 1];
        uint2 u0 = *(const uint2*)(g_ylh + (size_t)s0 * FEAT_CH + lane * 4);
        uint2 u1 = *(const uint2*)(g_ylh + (size_t)s1 * FEAT_CH + lane * 4);
        float2 a0 = __half22float2(*reinterpret_cast<__half2*>(&u0.x));
        float2 a1 = __half22float2(*reinterpret_cast<__half2*>(&u0.y));
        float2 c0 = __half22float2(*reinterpret_cast<__half2*>(&u1.x));
        float2 c1 = __half22float2(*reinterpret_cast<__half2*>(&u1.y));
        acc.x += a0.x + c0.x; acc.y += a0.y + c0.y;
        acc.z += a1.x + c1.x; acc.w += a1.y + c1.y;
    }
    if (e < end) {
        int s0 = g_csr[e];
        uint2 u0 = *(const uint2*)(g_ylh + (size_t)s0 * FEAT_CH + lane * 4);
        float2 a0 = __half22float2(*reinterpret_cast<__half2*>(&u0.x));
        float2 a1 = __half22float2(*reinterpret_cast<__half2*>(&u0.y));
        acc.x += a0.x; acc.y += a0.y; acc.z += a1.x; acc.w += a1.y;
    }
    float inv = 1.0f / (float)max(deg, 1);
    uint2 uy = *(const uint2*)(g_yrh + (size_t)node * 64 + lane * 2);
    float2 y0 = __half22float2(*reinterpret_cast<__half2*>(&uy.x));
    float2 y1 = __half22float2(*reinterpret_cast<__half2*>(&uy.y));
    float v0 = fmaxf(fmaf(acc.x, inv, bsv.x) + y0.x, 0.f);
    float v1 = fmaxf(fmaf(acc.y, inv, bsv.y) + y0.y, 0.f);
    float v2 = fmaxf(fmaf(acc.z, inv, bsv.z) + y1.x, 0.f);
    float v3 = fmaxf(fmaf(acc.w, inv, bsv.w) + y1.y, 0.f);
    *(uint2*)(g_vth + (size_t)node * 64 + lane * 2) =
        make_uint2(pack_f16x2(v0, v1), pack_f16x2(v2, v3));
}

// ---------------- kernel 4: final MLP (fc1 + BN + fc2) -----------------------
#define VTW 75
#define OFF_VT 0
#define OFF_W1 (256 * VTW)                 // 19200 words (16B aligned)
#define OFF_B1 (OFF_W1 + HIDDEN * FC1_IN)  // 24676
#define OFF_SC (OFF_B1 + HIDDEN)
#define OFF_TR (OFF_SC + HIDDEN)
#define OFF_W2 (OFF_TR + HIDDEN)
#define OFF_B2 (OFF_W2 + OUT_CH * HIDDEN)
#define FIN_WORDS (OFF_B2 + OUT_CH + 8)
#define FIN_SMEM (FIN_WORDS * 4)           // ~99.7 KB

__global__ void __launch_bounds__(256) final_kernel(
    const float* __restrict__ feats,
    const float* __restrict__ fc1_w, const float* __restrict__ fc1_b,
    const float* __restrict__ fc2_w, const float* __restrict__ fc2_b,
    const float* __restrict__ bn_g,  const float* __restrict__ bn_b,
    const float* __restrict__ bn_m,  const float* __restrict__ bn_v,
    float* __restrict__ out, int node_base)
{
    extern __shared__ __align__(16) uint32_t dyn[];
    uint32_t* vt = dyn + OFF_VT;
    float* w1s = (float*)(dyn + OFF_W1);
    float* b1 = (float*)(dyn + OFF_B1);
    float* sc = (float*)(dyn + OFF_SC);
    float* tr = (float*)(dyn + OFF_TR);
    float* w2s = (float*)(dyn + OFF_W2);
    float* b2 = (float*)(dyn + OFF_B2);

    int tid = threadIdx.x;
    int base = node_base + blockIdx.x * 256;

    for (int i = tid; i < HIDDEN * FC1_IN; i += 256) w1s[i] = fc1_w[i];
    for (int i = tid; i < OUT_CH * HIDDEN; i += 256) w2s[i] = fc2_w[i];
    if (tid < HIDDEN) {
        b1[tid] = fc1_b[tid];
        float s = bn_g[tid] * rsqrtf(bn_v[tid] + 1e-5f);
        sc[tid] = s;
        tr[tid] = bn_b[tid] - bn_m[tid] * s;
    }
    if (tid < OUT_CH) b2[tid] = fc2_b[tid];

#pragma unroll
    for (int it = 0; it < 32; it++) {
        int idx = tid + it * 256;            // 0..8191
        int n_off = idx >> 5;
        int q = idx & 31;
        int n = base + n_off;
        uint2 u = make_uint2(0u, 0u);
        if (n < N_NODES)
            u = *(const uint2*)(g_vth + (size_t)n * 64 + q * 2);
        vt[n_off * VTW + q * 2 + 0] = u.x;
        vt[n_off * VTW + q * 2 + 1] = u.y;
    }
    {
        int n = base + tid;
#pragma unroll
        for (int w = 0; w < 5; w++) {
            float4 e = make_float4(0.f, 0.f, 0.f, 0.f);
            if (n < N_NODES)
                e = *(const float4*)(feats + (size_t)n * FDIM + IN_SAGE + w * 4);
            vt[tid * VTW + 64 + w * 2 + 0] = pack_f16x2(e.x, e.y);
            vt[tid * VTW + 64 + w * 2 + 1] = pack_f16x2(e.z, e.w);
        }
    }
    __syncthreads();

    int node = base + tid;
    if (node >= N_NODES) return;

    float z[HIDDEN];
#pragma unroll
    for (int j = 0; j < HIDDEN; j++) z[j] = b1[j];

    const uint32_t* vrow = vt + tid * VTW;
    for (int g = 0; g < 37; g++) {
        uint32_t u0 = vrow[g * 2 + 0];
        uint32_t u1 = vrow[g * 2 + 1];
        float2 f0 = __half22float2(*reinterpret_cast<__half2*>(&u0));
        float2 f1 = __half22float2(*reinterpret_cast<__half2*>(&u1));
        const float4* wp = (const float4*)(w1s + g * 4);
#pragma unroll
        for (int j = 0; j < HIDDEN; j++) {
            float4 w = wp[j * 37];
            z[j] = fmaf(w.x, f0.x, z[j]);
            z[j] = fmaf(w.y, f0.y, z[j]);
            z[j] = fmaf(w.z, f1.x, z[j]);
            z[j] = fmaf(w.w, f1.y, z[j]);
        }
    }

    float h[HIDDEN];
#pragma unroll
    for (int j = 0; j < HIDDEN; j++)
        h[j] = fmaxf(z[j], 0.0f) * sc[j] + tr[j];
#pragma unroll
    for (int k = 0; k < OUT_CH; k++) {
        float s = b2[k];
#pragma unroll
        for (int j = 0; j < HIDDEN; j++)
            s = fmaf(w2s[k * HIDDEN + j], h[j], s);
        out[(size_t)node * OUT_CH + k] = s;
    }
}

// ---------------- launch ----------------------------------------------------
extern "C" void kernel_launch(void* const* d_in, const int* in_sizes, int n_in,
                              void* d_out, int out_size) {
    const float* features = (const float*)d_in[0];
    const int*   edges    = (const int*)  d_in[1];
    // d_in[2] = edges2 (unused), d_in[3] = edge_features (unused)
    const float* w_sage_l = (const float*)d_in[4];
    const float* b_sage_l = (const float*)d_in[5];
    const float* w_sage_r = (const float*)d_in[6];
    const float* fc1_w    = (const float*)d_in[7];
    const float* fc1_b    = (const float*)d_in[8];
    const float* fc2_w    = (const float*)d_in[9];
    const float* fc2_b    = (const float*)d_in[10];
    const float* bn_g     = (const float*)d_in[11];
    const float* bn_b     = (const float*)d_in[12];
    const float* bn_m     = (const float*)d_in[13];
    const float* bn_v     = (const float*)d_in[14];
    float* out = (float*)d_out;

    static cudaStream_t s1 = nullptr;
    static cudaEvent_t evFork = nullptr, evCSR = nullptr, evG0 = nullptr, evG1 = nullptr;
    if (s1 == nullptr) {
        cudaStreamCreateWithFlags(&s1, cudaStreamNonBlocking);
        cudaEventCreateWithFlags(&evFork, cudaEventDisableTiming);
        cudaEventCreateWithFlags(&evCSR, cudaEventDisableTiming);
        cudaEventCreateWithFlags(&evG0, cudaEventDisableTiming);
        cudaEventCreateWithFlags(&evG1, cudaEventDisableTiming);
    }

    cudaFuncSetAttribute(gemm_kernel,
                         cudaFuncAttributeMaxDynamicSharedMemorySize, GEMM_SMEM);
    cudaFuncSetAttribute(final_kernel,
                         cudaFuncAttributeMaxDynamicSharedMemorySize, FIN_SMEM);

    // fork: CSR build on s1, GEMM on default stream
    cudaEventRecord(evFork, 0);
    cudaStreamWaitEvent(s1, evFork, 0);

    zero_kernel<<<(N_NODES + 255) / 256, 256, 0, s1>>>();
    hist_kernel<<<(N_EDGES + 255) / 256, 256, 0, s1>>>(edges);
    scan1_kernel<<<NB, 256, 0, s1>>>();
    scan2_kernel<<<1, 512, 0, s1>>>();
    scan3_kernel<<<NB, 256, 0, s1>>>();
    fill_kernel<<<(N_EDGES + 255) / 256, 256, 0, s1>>>(edges);
    cudaEventRecord(evCSR, s1);

    prep_w_kernel<<<(256 * IN_SAGE) / 256, 256>>>(w_sage_l, w_sage_r);
    gemm_kernel<<<(N_NODES + GBM - 1) / GBM, 256, GEMM_SMEM>>>(features);

    // join CSR, then pipeline: gather0 -> (final0 || gather1) -> final1
    cudaStreamWaitEvent(0, evCSR, 0);

    gather_kernel<<<(HALF0 * 32 + 255) / 256, 256>>>(b_sage_l, 0, HALF0);
    cudaEventRecord(evG0, 0);

    cudaStreamWaitEvent(s1, evG0, 0);
    gather_kernel<<<(HALF1 * 32 + 255) / 256, 256, 0, s1>>>(b_sage_l, HALF0, HALF1);
    cudaEventRecord(evG1, s1);

    final_kernel<<<(HALF0 + 255) / 256, 256, FIN_SMEM>>>(
        features, fc1_w, fc1_b, fc2_w, fc2_b,
        bn_g, bn_b, bn_m, bn_v, out, 0);

    cudaStreamWaitEvent(0, evG1, 0);
    final_kernel<<<(HALF1 + 255) / 256, 256, FIN_SMEM>>>(
        features, fc1_w, fc1_b, fc2_w, fc2_b,
        bn_g, bn_b, bn_m, bn_v, out, HALF0);
}